// round 11
// baseline (speedup 1.0000x reference)
#include <cuda_runtime.h>
#include <mma.h>
#include <cstdint>
#include <cstddef>
#include <math.h>

using namespace nvcuda;

// ---------------- constants ----------------
// B=4, C=128, T=2000, K=31, H=512, N=B*T=8000
// BANDS = {2, 3x10, 8x12, 16x7, 17}; sum=257; O_k = 12*bw_k

__device__ const int d_bw[31]   = {2,3,3,3,3,3,3,3,3,3,3,
                                   8,8,8,8,8,8,8,8,8,8,8,8,
                                   16,16,16,16,16,16,16,17};
__device__ const int d_row0[31] = {0,2,5,8,11,14,17,20,23,26,29,
                                   32,40,48,56,64,72,80,88,96,104,112,
                                   120,128,144,160,176,192,208,224,240};

// ---------------- scratch ----------------
__device__ float g_xn[(size_t)31 * 8000 * 128];   // [k][n][c] normalized, tf32-rounded
// fc1 weights as contiguous 8x16 col-major tiles: [k][h16(32)][kk(16)][col(16)][row(8)]
__device__ float g_w1r[(size_t)31 * 512 * 128];
// fc2 weights as tiles: per band [o16(NT16)][jj(64)][col(16)][row(8)], o-padded
__device__ float g_w2r[(size_t)201 * 16 * 512];
__device__ float g_part[4 * 128 * 62];
__device__ float g_stats[4 * 31 * 2];             // (mean, invstd) per (b,k)
__device__ int   g_badOut;

// ---------------- helpers ----------------
__device__ __forceinline__ uint32_t to_tf32(float v) {
    uint32_t r;
    asm("cvt.rna.tf32.f32 %0, %1;" : "=r"(r) : "f"(v));
    return r;
}
__device__ __forceinline__ float fast_sigmoid(float x) {
    return __fdividef(1.f, 1.f + __expf(-x));
}
__device__ __forceinline__ float fast_tanh(float x) {
    float e = __expf(2.f * x);
    return 1.f - __fdividef(2.f, e + 1.f);
}
__device__ __forceinline__ void norm_wb(const float* nA, const float* nB, int i,
                                        float& wv, float& bv) {
    float va = nA[i], vb = nB[i];
    if (fabsf(va) >= fabsf(vb)) { wv = va; bv = vb; }
    else                        { wv = vb; bv = va; }
}

__global__ void resetK() { g_badOut = 0; }

// ---------------- stats (verified) ----------------
__global__ void stats1_kernel(const float* __restrict__ x) {
    int bc = blockIdx.x;
    const float* p = x + (size_t)bc * 2000 * 31;
    float s[31], q[31];
#pragma unroll
    for (int k = 0; k < 31; k++) { s[k] = 0.f; q[k] = 0.f; }
    for (int t = threadIdx.x; t < 2000; t += 256) {
        const float* pt = p + (size_t)t * 31;
#pragma unroll
        for (int k = 0; k < 31; k++) { float v = pt[k]; s[k] += v; q[k] += v * v; }
    }
    __shared__ float red[8][62];
    int lane = threadIdx.x & 31, w = threadIdx.x >> 5;
#pragma unroll
    for (int k = 0; k < 31; k++) {
#pragma unroll
        for (int o = 16; o; o >>= 1) {
            s[k] += __shfl_down_sync(0xFFFFFFFFu, s[k], o);
            q[k] += __shfl_down_sync(0xFFFFFFFFu, q[k], o);
        }
    }
    if (lane == 0) {
#pragma unroll
        for (int k = 0; k < 31; k++) { red[w][k] = s[k]; red[w][31 + k] = q[k]; }
    }
    __syncthreads();
    if (threadIdx.x < 62) {
        float acc = 0.f;
#pragma unroll
        for (int ww = 0; ww < 8; ww++) acc += red[ww][threadIdx.x];
        g_part[(size_t)bc * 62 + threadIdx.x] = acc;
    }
}

__global__ void stats2_kernel() {
    int b = blockIdx.x / 31, k = blockIdx.x % 31;
    int c = threadIdx.x;
    __shared__ float rs[128], rq[128];
    rs[c] = g_part[(size_t)(b * 128 + c) * 62 + k];
    rq[c] = g_part[(size_t)(b * 128 + c) * 62 + 31 + k];
    __syncthreads();
    for (int o = 64; o; o >>= 1) {
        if (c < o) { rs[c] += rs[c + o]; rq[c] += rq[c + o]; }
        __syncthreads();
    }
    if (c == 0) {
        float m = rs[0] * (1.f / 256000.f);
        float var = rq[0] * (1.f / 256000.f) - m * m;
        g_stats[(b * 31 + k) * 2] = m;
        g_stats[(b * 31 + k) * 2 + 1] = rsqrtf(var + 1e-5f);
    }
}

// ---------------- weight repack: contiguous 8x16 col-major tiles (ldm=8) ----------------
// g_w1r[i], i = ((((k*32 + h16)*16 + kk)*16 + col)*8 + row) = W1[k][h16*16+col][kk*8+row]
__global__ void refw1_kernel(const float* __restrict__ w1) {
    size_t i = (size_t)blockIdx.x * 256 + threadIdx.x;   // 7936*256 = 2,031,616
    int row = i & 7, col = (i >> 3) & 15, kk = (i >> 7) & 15,
        h16 = (i >> 11) & 31, k = i >> 16;
    float v = w1[((size_t)(k * 512 + h16 * 16 + col)) * 128 + kk * 8 + row];
    g_w1r[i] = __uint_as_float(to_tf32(v));
}
// per band: [o16][jj(64)][col(16)][row(8)]; element = W2pad[o16*16+col][jj*8+row]
__global__ void refw2_kernel(const float* __restrict__ w2) {
    int k = blockIdx.x, o16 = blockIdx.y;
    int O = 12 * d_bw[k];
    int NT16 = (O + 15) / 16;
    if (o16 >= NT16) return;
    size_t base = 0;
    for (int j = 0; j < k; j++) base += (size_t)((12 * d_bw[j] + 15) / 16) * 8192;
    base += (size_t)o16 * 8192;
    for (int i = threadIdx.x; i < 8192; i += 256) {
        int jj = i >> 7, rem = i & 127, col = rem >> 3, row = rem & 7;
        int o = o16 * 16 + col;
        float v = (o < O) ? w2[((size_t)k * 204 + o) * 512 + jj * 8 + row] : 0.f;
        g_w2r[base + i] = __uint_as_float(to_tf32(v));
    }
}

// ---------------- normT2 (verified R10): x[B,C,T,K] -> g_xn[k][n][c] ----------------
__global__ void __launch_bounds__(256) normT2(const float* __restrict__ x,
                                              const float* __restrict__ nA,
                                              const float* __restrict__ nB) {
    extern __shared__ float sm[];
    int t0 = blockIdx.x * 4, b = blockIdx.y;
    int tid = threadIdx.x;
    for (int idx = tid; idx < 128 * 124; idx += 256) {
        int c = idx / 124, rr = idx - c * 124;
        sm[rr * 129 + c] = x[(((size_t)(b * 128 + c)) * 2000 + t0) * 31 + rr];
    }
    __syncthreads();
    for (int idx = tid; idx < 124 * 128; idx += 256) {
        int rr = idx >> 7, c = idx & 127;
        int ti = rr / 31, k = rr - ti * 31;
        float mean = g_stats[(b * 31 + k) * 2];
        float inv  = g_stats[(b * 31 + k) * 2 + 1];
        float wv, bv;
        norm_wb(nA, nB, k * 128 + c, wv, bv);
        float v = (sm[rr * 129 + c] - mean) * inv * wv + bv;
        g_xn[((size_t)(k * 8000 + b * 2000 + t0 + ti)) * 128 + c] =
            __uint_as_float(to_tf32(v));
    }
}

// ---------------- fused main body (WMMA tf32), templated on band width ----------------
template <int BW>
__device__ __forceinline__ void mainBody(int k, const float* __restrict__ fb1,
                                         const float* __restrict__ fb2,
                                         float* __restrict__ out, float* sm) {
    constexpr int O = 12 * BW;
    constexpr int NT16 = (O + 15) / 16;
    constexpr int NTW = (NT16 + 3) / 4;
    constexpr int OP = NT16 * 16;
    constexpr int LD = 136;
    float* sx = sm;                       // [64][LD]
    float* sh = sm + 64 * LD;             // [64][LD]
    int n0 = blockIdx.x * 64;
    int tid = threadIdx.x, w = tid >> 5;
    int wt = w & 1, wo = w >> 1;

    int row0 = 0;
    size_t w2off = 0;
    for (int j = 0; j < k; j++) {
        row0 += d_bw[j];
        w2off += (size_t)((12 * d_bw[j] + 15) / 16) * 8192;
    }
    const float* w1b = g_w1r + (size_t)k * 512 * 128;
    const float* w2b = g_w2r + w2off;

    {
        const float4* src = (const float4*)(g_xn + ((size_t)k * 8000 + n0) * 128);
        for (int i = tid; i < 2048; i += 256) {
            int r = i >> 5, c4 = i & 31;
            *(float4*)&sx[r * LD + c4 * 4] = src[(size_t)r * 32 + c4];
        }
    }

    wmma::fragment<wmma::accumulator, 16, 16, 8, float> oc[2][NTW];
#pragma unroll
    for (int mt = 0; mt < 2; mt++)
#pragma unroll
        for (int i = 0; i < NTW; i++) wmma::fill_fragment(oc[mt][i], 0.f);
    __syncthreads();

#pragma unroll 1
    for (int ch = 0; ch < 4; ch++) {
        wmma::fragment<wmma::accumulator, 16, 16, 8, float> hc[2][2];
#pragma unroll
        for (int mt = 0; mt < 2; mt++)
#pragma unroll
            for (int nt = 0; nt < 2; nt++) wmma::fill_fragment(hc[mt][nt], 0.f);
#pragma unroll 4
        for (int kk = 0; kk < 16; kk++) {
            wmma::fragment<wmma::matrix_a, 16, 16, 8, wmma::precision::tf32, wmma::row_major> af[2];
#pragma unroll
            for (int mt = 0; mt < 2; mt++)
                wmma::load_matrix_sync(af[mt], &sx[(wt * 32 + mt * 16) * LD + kk * 8], LD);
#pragma unroll
            for (int nt = 0; nt < 2; nt++) {
                // tile (h16 = ch*8+wo*2+nt, kk), contiguous 8x16 col-major, ldm=8
                int h16 = ch * 8 + wo * 2 + nt;
                wmma::fragment<wmma::matrix_b, 16, 16, 8, wmma::precision::tf32, wmma::col_major> bf;
                wmma::load_matrix_sync(bf, w1b + ((size_t)(h16 * 16 + kk)) * 128, 8);
#pragma unroll
                for (int mt = 0; mt < 2; mt++) wmma::mma_sync(hc[mt][nt], af[mt], bf, hc[mt][nt]);
            }
        }
        __syncthreads();
#pragma unroll
        for (int mt = 0; mt < 2; mt++)
#pragma unroll
            for (int nt = 0; nt < 2; nt++)
                wmma::store_matrix_sync(&sh[(wt * 32 + mt * 16) * LD + wo * 32 + nt * 16],
                                        hc[mt][nt], LD, wmma::mem_row_major);
        __syncthreads();
        for (int i = tid; i < 8192; i += 256) {
            int r = i >> 7, cl = i & 127;
            float v = sh[r * LD + cl] + fb1[(size_t)k * 512 + ch * 128 + cl];
            sh[r * LD + cl] = __uint_as_float(to_tf32(fast_tanh(v)));
        }
        __syncthreads();
#pragma unroll 4
        for (int kk = 0; kk < 16; kk++) {
            wmma::fragment<wmma::matrix_a, 16, 16, 8, wmma::precision::tf32, wmma::row_major> af[2];
#pragma unroll
            for (int mt = 0; mt < 2; mt++)
                wmma::load_matrix_sync(af[mt], &sh[(wt * 32 + mt * 16) * LD + kk * 8], LD);
#pragma unroll
            for (int i = 0; i < NTW; i++) {
                int ot = wo + 4 * i;
                if (ot < NT16) {
                    // tile (o16 = ot, jj = ch*16+kk), ldm=8
                    wmma::fragment<wmma::matrix_b, 16, 16, 8, wmma::precision::tf32, wmma::col_major> bf;
                    wmma::load_matrix_sync(bf, w2b + ((size_t)(ot * 64 + ch * 16 + kk)) * 128, 8);
#pragma unroll
                    for (int mt = 0; mt < 2; mt++) wmma::mma_sync(oc[mt][i], af[mt], bf, oc[mt][i]);
                }
            }
        }
        __syncthreads();
    }

    float* so = sm;                      // [64][OP]
#pragma unroll
    for (int i = 0; i < NTW; i++) {
        int ot = wo + 4 * i;
        if (ot < NT16)
#pragma unroll
            for (int mt = 0; mt < 2; mt++)
                wmma::store_matrix_sync(&so[(wt * 32 + mt * 16) * OP + ot * 16],
                                        oc[mt][i], OP, wmma::mem_row_major);
    }
    __syncthreads();

    constexpr int U = 6 * BW;
    for (int idx = tid; idx < 64 * U; idx += 256) {
        int r = idx / U;
        int u = idx - r * U;
        float av = so[r * OP + u]     + fb2[(size_t)k * 204 + u];
        float gv = so[r * OP + u + U] + fb2[(size_t)k * 204 + u + U];
        float res = av * fast_sigmoid(gv);
        int nn = n0 + r;
        int b = nn / 2000;
        int t = nn - b * 2000;
        int ww = u / 6, v = u - ww * 6;
        out[((size_t)((b * 257 + row0 + ww) * 2000 + t)) * 6 + v] = res;
    }
}

// ---------------- single merged launch: grid (125, 31) ----------------
__global__ void __launch_bounds__(256) mainAll(const float* __restrict__ fb1,
                                               const float* __restrict__ fb2,
                                               float* __restrict__ out) {
    extern __shared__ float sm[];
    int k = blockIdx.y;
    switch (d_bw[k]) {
        case 2:  mainBody<2>(k, fb1, fb2, out, sm);  break;
        case 3:  mainBody<3>(k, fb1, fb2, out, sm);  break;
        case 8:  mainBody<8>(k, fb1, fb2, out, sm);  break;
        case 16: mainBody<16>(k, fb1, fb2, out, sm); break;
        default: mainBody<17>(k, fb1, fb2, out, sm); break;
    }
}

// ---------------- checker: validate sampled outputs against exact recompute ----------------
__global__ void checkOut(const float* __restrict__ x,
                         const float* __restrict__ nA, const float* __restrict__ nB,
                         const float* __restrict__ w1, const float* __restrict__ b1,
                         const float* __restrict__ w2, const float* __restrict__ b2,
                         const float* __restrict__ out) {
    __shared__ float sxn[128], shh[512];
    int k = blockIdx.x, s = blockIdx.y;
    int n = (s * 977 + k * 37 + 11) % 8000;
    int b = n / 2000, t = n - b * 2000;
    int bw = d_bw[k], U = 6 * bw, row0 = d_row0[k];
    int tid = threadIdx.x;
    if (tid < 128) {
        float mean = g_stats[(b * 31 + k) * 2];
        float inv  = g_stats[(b * 31 + k) * 2 + 1];
        float wv, bv;
        norm_wb(nA, nB, k * 128 + tid, wv, bv);
        sxn[tid] = (x[(((size_t)(b * 128 + tid)) * 2000 + t) * 31 + k] - mean) * inv * wv + bv;
    }
    __syncthreads();
    for (int hh = tid; hh < 512; hh += 256) {
        const float* wr = w1 + ((size_t)k * 512 + hh) * 128;
        float sacc = b1[k * 512 + hh];
        for (int c = 0; c < 128; c++) sacc += sxn[c] * wr[c];
        shh[hh] = tanhf(sacc);
    }
    __syncthreads();
    for (int u = tid; u < U; u += 256) {
        const float* wa = w2 + ((size_t)k * 204 + u) * 512;
        const float* wg = w2 + ((size_t)k * 204 + u + U) * 512;
        float a = b2[k * 204 + u], g = b2[k * 204 + u + U];
        for (int j = 0; j < 512; j++) { float hv = shh[j]; a += hv * wa[j]; g += hv * wg[j]; }
        float ref = a / (1.f + expf(-g));
        int ww = u / 6, v = u - ww * 6;
        float got = out[((size_t)((b * 257 + row0 + ww) * 2000 + t)) * 6 + v];
        if (fabsf(got - ref) > 0.05f + 0.05f * fabsf(ref)) atomicExch(&g_badOut, 1);
    }
}

// ---------------- guarded naive fallback (verified R9) ----------------
__global__ void __launch_bounds__(256) naiveK(
    const float* __restrict__ x,
    const float* __restrict__ nA, const float* __restrict__ nB,
    const float* __restrict__ w1, const float* __restrict__ b1,
    const float* __restrict__ w2, const float* __restrict__ b2,
    float* __restrict__ out)
{
    if (!g_badOut) return;
    extern __shared__ float sm[];
    float* sxn = sm;                 // [32][132]
    float* sh  = sm + 32 * 132;      // [32][516]
    int k = blockIdx.y;
    int tile = blockIdx.x;
    int bw = d_bw[k];
    int U = 6 * bw;
    int row0 = d_row0[k];
    int tid = threadIdx.x;

    for (int e = tid; e < 32 * 128; e += 256) {
        int i = e >> 7, c = e & 127;
        int n = tile * 32 + i;
        int b = n / 2000, t = n - b * 2000;
        float mean = g_stats[(b * 31 + k) * 2];
        float inv  = g_stats[(b * 31 + k) * 2 + 1];
        float wv, bv;
        norm_wb(nA, nB, k * 128 + c, wv, bv);
        float v = x[(((size_t)(b * 128 + c)) * 2000 + t) * 31 + k];
        sxn[i * 132 + c] = (v - mean) * inv * wv + bv;
    }
    __syncthreads();
    for (int idx = tid; idx < 32 * 512; idx += 256) {
        int hh = idx >> 5, i = idx & 31;
        const float* wr = w1 + ((size_t)k * 512 + hh) * 128;
        float s = b1[k * 512 + hh];
#pragma unroll 8
        for (int c = 0; c < 128; c++) s += sxn[i * 132 + c] * wr[c];
        sh[i * 516 + hh] = tanhf(s);
    }
    __syncthreads();
    for (int idx = tid; idx < 32 * U; idx += 256) {
        int i = idx / U, u = idx - i * U;
        const float* wa = w2 + ((size_t)k * 204 + u) * 512;
        const float* wg = w2 + ((size_t)k * 204 + u + U) * 512;
        float a = b2[k * 204 + u];
        float g = b2[k * 204 + u + U];
#pragma unroll 8
        for (int j = 0; j < 512; j++) {
            float hv = sh[i * 516 + j];
            a += hv * wa[j];
            g += hv * wg[j];
        }
        float res = a / (1.f + expf(-g));
        int n = tile * 32 + i;
        int b = n / 2000, t = n - b * 2000;
        int ww = u / 6, v = u - ww * 6;
        out[((size_t)((b * 257 + row0 + ww) * 2000 + t)) * 6 + v] = res;
    }
}

// ---------------- launch ----------------
extern "C" void kernel_launch(void* const* d_in, const int* in_sizes, int n_in,
                              void* d_out, int out_size) {
    const float* x  = (const float*)d_in[0];
    const float* nA = (const float*)d_in[1];
    const float* nB = (const float*)d_in[2];
    const float* w1 = (const float*)d_in[3];
    const float* b1 = (const float*)d_in[4];
    const float* w2 = (const float*)d_in[5];
    const float* b2 = (const float*)d_in[6];
    float* out = (float*)d_out;

    const int SMEM_T2 = 124 * 129 * 4;               // 63,984 B
    const int SMEM_MK = 2 * 64 * 136 * 4;            // 69,632 B
    const int SMEM_NV = (32 * 132 + 32 * 516) * 4;   // 82,944 B

    cudaFuncSetAttribute(normT2,  cudaFuncAttributeMaxDynamicSharedMemorySize, SMEM_T2);
    cudaFuncSetAttribute(mainAll, cudaFuncAttributeMaxDynamicSharedMemorySize, SMEM_MK);
    cudaFuncSetAttribute(naiveK,  cudaFuncAttributeMaxDynamicSharedMemorySize, SMEM_NV);

    resetK<<<1, 1>>>();
    stats1_kernel<<<512, 256>>>(x);
    stats2_kernel<<<124, 128>>>();
    refw1_kernel<<<7936, 256>>>(w1);
    refw2_kernel<<<dim3(31, 13), 256>>>(w2);
    normT2<<<dim3(500, 4), 256, SMEM_T2>>>(x, nA, nB);

    mainAll<<<dim3(125, 31), 256, SMEM_MK>>>(b1, b2, out);

    checkOut<<<dim3(31, 8), 256>>>(x, nA, nB, w1, b1, w2, b2, out);
    naiveK<<<dim3(250, 31), 256, SMEM_NV>>>(x, nA, nB, w1, b1, w2, b2, out);
}

// round 12
// speedup vs baseline: 1.0634x; 1.0634x over previous
#include <cuda_runtime.h>
#include <mma.h>
#include <cstdint>
#include <cstddef>
#include <math.h>

using namespace nvcuda;

// ---------------- constants ----------------
// B=4, C=128, T=2000, K=31, H=512, N=B*T=8000
// BANDS = {2, 3x10, 8x12, 16x7, 17}; sum=257; O_k = 12*bw_k

__device__ const int d_bw[31]   = {2,3,3,3,3,3,3,3,3,3,3,
                                   8,8,8,8,8,8,8,8,8,8,8,8,
                                   16,16,16,16,16,16,16,17};
__device__ const int d_row0[31] = {0,2,5,8,11,14,17,20,23,26,29,
                                   32,40,48,56,64,72,80,88,96,104,112,
                                   120,128,144,160,176,192,208,224,240};

// ---------------- scratch ----------------
__device__ float g_xn[(size_t)31 * 8000 * 128];   // [k][n][c] normalized, tf32-rounded
// fc1 weights as contiguous 8x16 col-major tiles: [k][h16(32)][kk(16)][col(16)][row(8)]
__device__ float g_w1r[(size_t)31 * 512 * 128];
// fc2 weights as tiles: per band [o16(NT16)][jj(64)][col(16)][row(8)], o-padded
__device__ float g_w2r[(size_t)201 * 16 * 512];
__device__ float g_part[4 * 128 * 62];
__device__ float g_stats[4 * 31 * 2];             // (mean, invstd) per (b,k)
__device__ int   g_badOut;

// ---------------- helpers ----------------
__device__ __forceinline__ uint32_t to_tf32(float v) {
    uint32_t r;
    asm("cvt.rna.tf32.f32 %0, %1;" : "=r"(r) : "f"(v));
    return r;
}
__device__ __forceinline__ float fast_sigmoid(float x) {
    return __fdividef(1.f, 1.f + __expf(-x));
}
__device__ __forceinline__ float fast_tanh(float x) {
    float e = __expf(2.f * x);
    return 1.f - __fdividef(2.f, e + 1.f);
}
__device__ __forceinline__ void norm_wb(const float* nA, const float* nB, int i,
                                        float& wv, float& bv) {
    float va = nA[i], vb = nB[i];
    if (fabsf(va) >= fabsf(vb)) { wv = va; bv = vb; }
    else                        { wv = vb; bv = va; }
}

__global__ void resetK() { g_badOut = 0; }

// ---------------- stats (verified) ----------------
__global__ void stats1_kernel(const float* __restrict__ x) {
    int bc = blockIdx.x;
    const float* p = x + (size_t)bc * 2000 * 31;
    float s[31], q[31];
#pragma unroll
    for (int k = 0; k < 31; k++) { s[k] = 0.f; q[k] = 0.f; }
    for (int t = threadIdx.x; t < 2000; t += 256) {
        const float* pt = p + (size_t)t * 31;
#pragma unroll
        for (int k = 0; k < 31; k++) { float v = pt[k]; s[k] += v; q[k] += v * v; }
    }
    __shared__ float red[8][62];
    int lane = threadIdx.x & 31, w = threadIdx.x >> 5;
#pragma unroll
    for (int k = 0; k < 31; k++) {
#pragma unroll
        for (int o = 16; o; o >>= 1) {
            s[k] += __shfl_down_sync(0xFFFFFFFFu, s[k], o);
            q[k] += __shfl_down_sync(0xFFFFFFFFu, q[k], o);
        }
    }
    if (lane == 0) {
#pragma unroll
        for (int k = 0; k < 31; k++) { red[w][k] = s[k]; red[w][31 + k] = q[k]; }
    }
    __syncthreads();
    if (threadIdx.x < 62) {
        float acc = 0.f;
#pragma unroll
        for (int ww = 0; ww < 8; ww++) acc += red[ww][threadIdx.x];
        g_part[(size_t)bc * 62 + threadIdx.x] = acc;
    }
}

__global__ void stats2_kernel() {
    int b = blockIdx.x / 31, k = blockIdx.x % 31;
    int c = threadIdx.x;
    __shared__ float rs[128], rq[128];
    rs[c] = g_part[(size_t)(b * 128 + c) * 62 + k];
    rq[c] = g_part[(size_t)(b * 128 + c) * 62 + 31 + k];
    __syncthreads();
    for (int o = 64; o; o >>= 1) {
        if (c < o) { rs[c] += rs[c + o]; rq[c] += rq[c + o]; }
        __syncthreads();
    }
    if (c == 0) {
        float m = rs[0] * (1.f / 256000.f);
        float var = rq[0] * (1.f / 256000.f) - m * m;
        g_stats[(b * 31 + k) * 2] = m;
        g_stats[(b * 31 + k) * 2 + 1] = rsqrtf(var + 1e-5f);
    }
}

// ---------------- weight repack: contiguous 8x16 col-major tiles (ldm=8) ----------------
__global__ void refw1_kernel(const float* __restrict__ w1) {
    size_t i = (size_t)blockIdx.x * 256 + threadIdx.x;   // 7936*256 = 2,031,616
    int row = i & 7, col = (i >> 3) & 15, kk = (i >> 7) & 15,
        h16 = (i >> 11) & 31, k = i >> 16;
    float v = w1[((size_t)(k * 512 + h16 * 16 + col)) * 128 + kk * 8 + row];
    g_w1r[i] = __uint_as_float(to_tf32(v));
}
__global__ void refw2_kernel(const float* __restrict__ w2) {
    int k = blockIdx.x, o16 = blockIdx.y;
    int O = 12 * d_bw[k];
    int NT16 = (O + 15) / 16;
    if (o16 >= NT16) return;
    size_t base = 0;
    for (int j = 0; j < k; j++) base += (size_t)((12 * d_bw[j] + 15) / 16) * 8192;
    base += (size_t)o16 * 8192;
    for (int i = threadIdx.x; i < 8192; i += 256) {
        int jj = i >> 7, rem = i & 127, col = rem >> 3, row = rem & 7;
        int o = o16 * 16 + col;
        float v = (o < O) ? w2[((size_t)k * 204 + o) * 512 + jj * 8 + row] : 0.f;
        g_w2r[base + i] = __uint_as_float(to_tf32(v));
    }
}

// ---------------- normT2 (verified R10): x[B,C,T,K] -> g_xn[k][n][c] ----------------
__global__ void __launch_bounds__(256) normT2(const float* __restrict__ x,
                                              const float* __restrict__ nA,
                                              const float* __restrict__ nB) {
    extern __shared__ float sm[];
    int t0 = blockIdx.x * 4, b = blockIdx.y;
    int tid = threadIdx.x;
    for (int idx = tid; idx < 128 * 124; idx += 256) {
        int c = idx / 124, rr = idx - c * 124;
        sm[rr * 129 + c] = x[(((size_t)(b * 128 + c)) * 2000 + t0) * 31 + rr];
    }
    __syncthreads();
    for (int idx = tid; idx < 124 * 128; idx += 256) {
        int rr = idx >> 7, c = idx & 127;
        int ti = rr / 31, k = rr - ti * 31;
        float mean = g_stats[(b * 31 + k) * 2];
        float inv  = g_stats[(b * 31 + k) * 2 + 1];
        float wv, bv;
        norm_wb(nA, nB, k * 128 + c, wv, bv);
        float v = (sm[rr * 129 + c] - mean) * inv * wv + bv;
        g_xn[((size_t)(k * 8000 + b * 2000 + t0 + ti)) * 128 + c] =
            __uint_as_float(to_tf32(v));
    }
}

// ---------------- fused main kernel (WMMA tf32), 512 threads, 1 m-frag/warp ----------------
// warps: wt = w&3 (token quarter of 16 rows), wo = w>>2 (H/O group of 4)
template <int BW>
__global__ void __launch_bounds__(512) mainK(const float* __restrict__ fb1,
                                             const float* __restrict__ fb2,
                                             float* __restrict__ out, int k0) {
    constexpr int O = 12 * BW;
    constexpr int NT16 = (O + 15) / 16;
    constexpr int NTW = (NT16 + 3) / 4;
    constexpr int OP = NT16 * 16;
    constexpr int LD = 136;
    extern __shared__ float sm[];
    float* sx = sm;                       // [64][LD]
    float* sh = sm + 64 * LD;             // [64][LD]
    int k = k0 + blockIdx.y;
    int n0 = blockIdx.x * 64;
    int tid = threadIdx.x, w = tid >> 5;
    int wt = w & 3, wo = w >> 2;
    int r0 = wt * 16;

    int row0 = 0;
    size_t w2off = 0;
    for (int j = 0; j < k; j++) {
        row0 += d_bw[j];
        w2off += (size_t)((12 * d_bw[j] + 15) / 16) * 8192;
    }
    const float* w1b = g_w1r + (size_t)k * 512 * 128;
    const float* w2b = g_w2r + w2off;

    {
        const float4* src = (const float4*)(g_xn + ((size_t)k * 8000 + n0) * 128);
        for (int i = tid; i < 2048; i += 512) {
            int r = i >> 5, c4 = i & 31;
            *(float4*)&sx[r * LD + c4 * 4] = src[(size_t)r * 32 + c4];
        }
    }

    wmma::fragment<wmma::accumulator, 16, 16, 8, float> oc[NTW];
#pragma unroll
    for (int i = 0; i < NTW; i++) wmma::fill_fragment(oc[i], 0.f);
    __syncthreads();

#pragma unroll 1
    for (int ch = 0; ch < 4; ch++) {
        // ---- fc1: rows [r0,+16) x H cols [ch*128 + wo*32, +32) ----
        wmma::fragment<wmma::accumulator, 16, 16, 8, float> hc[2];
#pragma unroll
        for (int nt = 0; nt < 2; nt++) wmma::fill_fragment(hc[nt], 0.f);
#pragma unroll 4
        for (int kk = 0; kk < 16; kk++) {
            wmma::fragment<wmma::matrix_a, 16, 16, 8, wmma::precision::tf32, wmma::row_major> af;
            wmma::load_matrix_sync(af, &sx[r0 * LD + kk * 8], LD);
#pragma unroll
            for (int nt = 0; nt < 2; nt++) {
                int h16 = ch * 8 + wo * 2 + nt;
                wmma::fragment<wmma::matrix_b, 16, 16, 8, wmma::precision::tf32, wmma::col_major> bf;
                wmma::load_matrix_sync(bf, w1b + ((size_t)(h16 * 16 + kk)) * 128, 8);
                wmma::mma_sync(hc[nt], af, bf, hc[nt]);
            }
        }
        __syncthreads();   // previous chunk's fc2 reads of sh done
#pragma unroll
        for (int nt = 0; nt < 2; nt++)
            wmma::store_matrix_sync(&sh[r0 * LD + wo * 32 + nt * 16], hc[nt], LD,
                                    wmma::mem_row_major);
        __syncthreads();
        // ---- elementwise: bias + tanh + tf32 round ----
        for (int i = tid; i < 8192; i += 512) {
            int r = i >> 7, cl = i & 127;
            float v = sh[r * LD + cl] + fb1[(size_t)k * 512 + ch * 128 + cl];
            sh[r * LD + cl] = __uint_as_float(to_tf32(fast_tanh(v)));
        }
        __syncthreads();
        // ---- fc2 partial over this chunk's 128 j ----
#pragma unroll 4
        for (int kk = 0; kk < 16; kk++) {
            wmma::fragment<wmma::matrix_a, 16, 16, 8, wmma::precision::tf32, wmma::row_major> af;
            wmma::load_matrix_sync(af, &sh[r0 * LD + kk * 8], LD);
#pragma unroll
            for (int i = 0; i < NTW; i++) {
                int ot = wo + 4 * i;
                if (ot < NT16) {
                    wmma::fragment<wmma::matrix_b, 16, 16, 8, wmma::precision::tf32, wmma::col_major> bf;
                    wmma::load_matrix_sync(bf, w2b + ((size_t)(ot * 64 + ch * 16 + kk)) * 128, 8);
                    wmma::mma_sync(oc[i], af, bf, oc[i]);
                }
            }
        }
        __syncthreads();
    }

    // ---- epilogue ----
    float* so = sm;                      // [64][OP]
#pragma unroll
    for (int i = 0; i < NTW; i++) {
        int ot = wo + 4 * i;
        if (ot < NT16)
            wmma::store_matrix_sync(&so[r0 * OP + ot * 16], oc[i], OP, wmma::mem_row_major);
    }
    __syncthreads();

    constexpr int U = 6 * BW;
    for (int idx = tid; idx < 64 * U; idx += 512) {
        int r = idx / U;
        int u = idx - r * U;
        float av = so[r * OP + u]     + fb2[(size_t)k * 204 + u];
        float gv = so[r * OP + u + U] + fb2[(size_t)k * 204 + u + U];
        float res = av * fast_sigmoid(gv);
        int nn = n0 + r;
        int b = nn / 2000;
        int t = nn - b * 2000;
        int ww = u / 6, v = u - ww * 6;
        out[((size_t)((b * 257 + row0 + ww) * 2000 + t)) * 6 + v] = res;
    }
}

// ---------------- checker: validate sampled outputs against exact recompute ----------------
__global__ void checkOut(const float* __restrict__ x,
                         const float* __restrict__ nA, const float* __restrict__ nB,
                         const float* __restrict__ w1, const float* __restrict__ b1,
                         const float* __restrict__ w2, const float* __restrict__ b2,
                         const float* __restrict__ out) {
    __shared__ float sxn[128], shh[512];
    int k = blockIdx.x, s = blockIdx.y;
    int n = (s * 977 + k * 37 + 11) % 8000;
    int b = n / 2000, t = n - b * 2000;
    int bw = d_bw[k], U = 6 * bw, row0 = d_row0[k];
    int tid = threadIdx.x;
    if (tid < 128) {
        float mean = g_stats[(b * 31 + k) * 2];
        float inv  = g_stats[(b * 31 + k) * 2 + 1];
        float wv, bv;
        norm_wb(nA, nB, k * 128 + tid, wv, bv);
        sxn[tid] = (x[(((size_t)(b * 128 + tid)) * 2000 + t) * 31 + k] - mean) * inv * wv + bv;
    }
    __syncthreads();
    for (int hh = tid; hh < 512; hh += 256) {
        const float* wr = w1 + ((size_t)k * 512 + hh) * 128;
        float sacc = b1[k * 512 + hh];
        for (int c = 0; c < 128; c++) sacc += sxn[c] * wr[c];
        shh[hh] = tanhf(sacc);
    }
    __syncthreads();
    for (int u = tid; u < U; u += 256) {
        const float* wa = w2 + ((size_t)k * 204 + u) * 512;
        const float* wg = w2 + ((size_t)k * 204 + u + U) * 512;
        float a = b2[k * 204 + u], g = b2[k * 204 + u + U];
        for (int j = 0; j < 512; j++) { float hv = shh[j]; a += hv * wa[j]; g += hv * wg[j]; }
        float ref = a / (1.f + expf(-g));
        int ww = u / 6, v = u - ww * 6;
        float got = out[((size_t)((b * 257 + row0 + ww) * 2000 + t)) * 6 + v];
        if (fabsf(got - ref) > 0.05f + 0.05f * fabsf(ref)) atomicExch(&g_badOut, 1);
    }
}

// ---------------- guarded naive fallback (verified R9) ----------------
__global__ void __launch_bounds__(256) naiveK(
    const float* __restrict__ x,
    const float* __restrict__ nA, const float* __restrict__ nB,
    const float* __restrict__ w1, const float* __restrict__ b1,
    const float* __restrict__ w2, const float* __restrict__ b2,
    float* __restrict__ out)
{
    if (!g_badOut) return;
    extern __shared__ float sm[];
    float* sxn = sm;                 // [32][132]
    float* sh  = sm + 32 * 132;      // [32][516]
    int k = blockIdx.y;
    int tile = blockIdx.x;
    int bw = d_bw[k];
    int U = 6 * bw;
    int row0 = d_row0[k];
    int tid = threadIdx.x;

    for (int e = tid; e < 32 * 128; e += 256) {
        int i = e >> 7, c = e & 127;
        int n = tile * 32 + i;
        int b = n / 2000, t = n - b * 2000;
        float mean = g_stats[(b * 31 + k) * 2];
        float inv  = g_stats[(b * 31 + k) * 2 + 1];
        float wv, bv;
        norm_wb(nA, nB, k * 128 + c, wv, bv);
        float v = x[(((size_t)(b * 128 + c)) * 2000 + t) * 31 + k];
        sxn[i * 132 + c] = (v - mean) * inv * wv + bv;
    }
    __syncthreads();
    for (int idx = tid; idx < 32 * 512; idx += 256) {
        int hh = idx >> 5, i = idx & 31;
        const float* wr = w1 + ((size_t)k * 512 + hh) * 128;
        float s = b1[k * 512 + hh];
#pragma unroll 8
        for (int c = 0; c < 128; c++) s += sxn[i * 132 + c] * wr[c];
        sh[i * 516 + hh] = tanhf(s);
    }
    __syncthreads();
    for (int idx = tid; idx < 32 * U; idx += 256) {
        int i = idx / U, u = idx - i * U;
        const float* wa = w2 + ((size_t)k * 204 + u) * 512;
        const float* wg = w2 + ((size_t)k * 204 + u + U) * 512;
        float a = b2[k * 204 + u];
        float g = b2[k * 204 + u + U];
#pragma unroll 8
        for (int j = 0; j < 512; j++) {
            float hv = sh[i * 516 + j];
            a += hv * wa[j];
            g += hv * wg[j];
        }
        float res = a / (1.f + expf(-g));
        int n = tile * 32 + i;
        int b = n / 2000, t = n - b * 2000;
        int ww = u / 6, v = u - ww * 6;
        out[((size_t)((b * 257 + row0 + ww) * 2000 + t)) * 6 + v] = res;
    }
}

// ---------------- launch ----------------
extern "C" void kernel_launch(void* const* d_in, const int* in_sizes, int n_in,
                              void* d_out, int out_size) {
    const float* x  = (const float*)d_in[0];
    const float* nA = (const float*)d_in[1];
    const float* nB = (const float*)d_in[2];
    const float* w1 = (const float*)d_in[3];
    const float* b1 = (const float*)d_in[4];
    const float* w2 = (const float*)d_in[5];
    const float* b2 = (const float*)d_in[6];
    float* out = (float*)d_out;

    const int SMEM_T2 = 124 * 129 * 4;               // 63,984 B
    const int SMEM_MK = 2 * 64 * 136 * 4;            // 69,632 B
    const int SMEM_NV = (32 * 132 + 32 * 516) * 4;   // 82,944 B

    cudaFuncSetAttribute(normT2,    cudaFuncAttributeMaxDynamicSharedMemorySize, SMEM_T2);
    cudaFuncSetAttribute(mainK<2>,  cudaFuncAttributeMaxDynamicSharedMemorySize, SMEM_MK);
    cudaFuncSetAttribute(mainK<3>,  cudaFuncAttributeMaxDynamicSharedMemorySize, SMEM_MK);
    cudaFuncSetAttribute(mainK<8>,  cudaFuncAttributeMaxDynamicSharedMemorySize, SMEM_MK);
    cudaFuncSetAttribute(mainK<16>, cudaFuncAttributeMaxDynamicSharedMemorySize, SMEM_MK);
    cudaFuncSetAttribute(mainK<17>, cudaFuncAttributeMaxDynamicSharedMemorySize, SMEM_MK);
    cudaFuncSetAttribute(naiveK,    cudaFuncAttributeMaxDynamicSharedMemorySize, SMEM_NV);

    resetK<<<1, 1>>>();
    stats1_kernel<<<512, 256>>>(x);
    stats2_kernel<<<124, 128>>>();
    refw1_kernel<<<7936, 256>>>(w1);
    refw2_kernel<<<dim3(31, 13), 256>>>(w2);
    normT2<<<dim3(500, 4), 256, SMEM_T2>>>(x, nA, nB);

    mainK<2><<<dim3(125, 1), 512, SMEM_MK>>>(b1, b2, out, 0);
    mainK<3><<<dim3(125, 10), 512, SMEM_MK>>>(b1, b2, out, 1);
    mainK<8><<<dim3(125, 12), 512, SMEM_MK>>>(b1, b2, out, 11);
    mainK<16><<<dim3(125, 7), 512, SMEM_MK>>>(b1, b2, out, 23);
    mainK<17><<<dim3(125, 1), 512, SMEM_MK>>>(b1, b2, out, 30);

    checkOut<<<dim3(31, 8), 256>>>(x, nA, nB, w1, b1, w2, b2, out);
    naiveK<<<dim3(250, 31), 256, SMEM_NV>>>(x, nA, nB, w1, b1, w2, b2, out);
}

// round 13
// speedup vs baseline: 2.4913x; 2.3427x over previous
#include <cuda_runtime.h>
#include <cuda_fp16.h>
#include <mma.h>
#include <cstdint>
#include <cstddef>
#include <math.h>

using namespace nvcuda;

// ---------------- constants ----------------
// B=4, C=128, T=2000, K=31, H=512, N=B*T=8000
// BANDS = {2, 3x10, 8x12, 16x7, 17}; sum=257; O_k = 12*bw_k

__device__ const int d_bw[31]   = {2,3,3,3,3,3,3,3,3,3,3,
                                   8,8,8,8,8,8,8,8,8,8,8,8,
                                   16,16,16,16,16,16,16,17};
__device__ const int d_row0[31] = {0,2,5,8,11,14,17,20,23,26,29,
                                   32,40,48,56,64,72,80,88,96,104,112,
                                   120,128,144,160,176,192,208,224,240};

// ---------------- scratch ----------------
__device__ __half g_xnh[(size_t)31 * 8000 * 128];   // normalized input f16 [k][n][c]
__device__ __half g_h[(size_t)31 * 8000 * 512];     // fc1+tanh output f16 [k][n][h]
__device__ __half g_w1h[(size_t)31 * 512 * 128];    // fc1 weights f16, natural [k][h][c]
__device__ __half g_w2h[(size_t)201 * 16 * 512];    // fc2 weights f16, per-band o-padded [o][j]
__device__ float  g_part[4 * 128 * 62];
__device__ float  g_stats[4 * 31 * 2];              // (mean, invstd) per (b,k)
__device__ int    g_badOut;

// ---------------- helpers ----------------
__device__ __forceinline__ float fast_sigmoid(float x) {
    return __fdividef(1.f, 1.f + __expf(-x));
}
__device__ __forceinline__ float fast_tanh(float x) {
    float e = __expf(2.f * x);
    return 1.f - __fdividef(2.f, e + 1.f);
}
__device__ __forceinline__ void norm_wb(const float* nA, const float* nB, int i,
                                        float& wv, float& bv) {
    float va = nA[i], vb = nB[i];
    if (fabsf(va) >= fabsf(vb)) { wv = va; bv = vb; }
    else                        { wv = vb; bv = va; }
}

__global__ void resetK() { g_badOut = 0; }

// ---------------- stats (verified) ----------------
__global__ void stats1_kernel(const float* __restrict__ x) {
    int bc = blockIdx.x;
    const float* p = x + (size_t)bc * 2000 * 31;
    float s[31], q[31];
#pragma unroll
    for (int k = 0; k < 31; k++) { s[k] = 0.f; q[k] = 0.f; }
    for (int t = threadIdx.x; t < 2000; t += 256) {
        const float* pt = p + (size_t)t * 31;
#pragma unroll
        for (int k = 0; k < 31; k++) { float v = pt[k]; s[k] += v; q[k] += v * v; }
    }
    __shared__ float red[8][62];
    int lane = threadIdx.x & 31, w = threadIdx.x >> 5;
#pragma unroll
    for (int k = 0; k < 31; k++) {
#pragma unroll
        for (int o = 16; o; o >>= 1) {
            s[k] += __shfl_down_sync(0xFFFFFFFFu, s[k], o);
            q[k] += __shfl_down_sync(0xFFFFFFFFu, q[k], o);
        }
    }
    if (lane == 0) {
#pragma unroll
        for (int k = 0; k < 31; k++) { red[w][k] = s[k]; red[w][31 + k] = q[k]; }
    }
    __syncthreads();
    if (threadIdx.x < 62) {
        float acc = 0.f;
#pragma unroll
        for (int ww = 0; ww < 8; ww++) acc += red[ww][threadIdx.x];
        g_part[(size_t)bc * 62 + threadIdx.x] = acc;
    }
}

__global__ void stats2_kernel() {
    int b = blockIdx.x / 31, k = blockIdx.x % 31;
    int c = threadIdx.x;
    __shared__ float rs[128], rq[128];
    rs[c] = g_part[(size_t)(b * 128 + c) * 62 + k];
    rq[c] = g_part[(size_t)(b * 128 + c) * 62 + 31 + k];
    __syncthreads();
    for (int o = 64; o; o >>= 1) {
        if (c < o) { rs[c] += rs[c + o]; rq[c] += rq[c + o]; }
        __syncthreads();
    }
    if (c == 0) {
        float m = rs[0] * (1.f / 256000.f);
        float var = rq[0] * (1.f / 256000.f) - m * m;
        g_stats[(b * 31 + k) * 2] = m;
        g_stats[(b * 31 + k) * 2 + 1] = rsqrtf(var + 1e-5f);
    }
}

// ---------------- weight converts ----------------
__global__ void refw1h(const float* __restrict__ w1) {
    size_t i = (size_t)blockIdx.x * 256 + threadIdx.x;   // 7936*256 = 2,031,616
    g_w1h[i] = __float2half(w1[i]);
}
__global__ void refw2h(const float* __restrict__ w2) {
    int k = blockIdx.x, o16 = blockIdx.y;
    int O = 12 * d_bw[k];
    int NT16 = (O + 15) / 16;
    if (o16 >= NT16) return;
    int offRows = 0;
    for (int j = 0; j < k; j++) offRows += ((12 * d_bw[j] + 15) / 16) * 16;
    __half* dst = g_w2h + ((size_t)(offRows + o16 * 16)) * 512;
    for (int i = threadIdx.x; i < 16 * 512; i += 256) {
        int r = i >> 9, j = i & 511;
        int o = o16 * 16 + r;
        float v = (o < O) ? w2[((size_t)k * 204 + o) * 512 + j] : 0.f;
        dst[(size_t)r * 512 + j] = __float2half(v);
    }
}

// ---------------- normT2h (verified structure): x[B,C,T,K] -> g_xnh[k][n][c] ----------------
__global__ void __launch_bounds__(256) normT2h(const float* __restrict__ x,
                                               const float* __restrict__ nA,
                                               const float* __restrict__ nB) {
    extern __shared__ float sm[];
    int t0 = blockIdx.x * 4, b = blockIdx.y;
    int tid = threadIdx.x;
    for (int idx = tid; idx < 128 * 124; idx += 256) {
        int c = idx / 124, rr = idx - c * 124;
        sm[rr * 129 + c] = x[(((size_t)(b * 128 + c)) * 2000 + t0) * 31 + rr];
    }
    __syncthreads();
    for (int idx = tid; idx < 124 * 128; idx += 256) {
        int rr = idx >> 7, c = idx & 127;
        int ti = rr / 31, k = rr - ti * 31;
        float mean = g_stats[(b * 31 + k) * 2];
        float inv  = g_stats[(b * 31 + k) * 2 + 1];
        float wv, bv;
        norm_wb(nA, nB, k * 128 + c, wv, bv);
        float v = (sm[rr * 129 + c] - mean) * inv * wv + bv;
        g_xnh[((size_t)(k * 8000 + b * 2000 + t0 + ti)) * 128 + c] = __float2half(v);
    }
}

// ---------------- pass A: fc1 + tanh (f16 mma, smem-staged) ----------------
// grid (63, 31), 512 threads = 16 warps (wt 0..3 token 32-rows, wo 0..3 h 32-cols of chunk)
__global__ void __launch_bounds__(512, 2) fc1K(const float* __restrict__ fb1) {
    extern __shared__ char smraw[];
    __half* sxn = (__half*)smraw;               // [128][136] f16: 34816 B
    __half* sw  = (__half*)(smraw + 34816);     // [128][136] f16: 34816 B
    float*  swf = (float*)(smraw + 34816);      // f32 view [128][68] for epilogue reuse
    int k = blockIdx.y;
    int n0 = blockIdx.x * 128;
    int tid = threadIdx.x, w = tid >> 5;
    int wt = w & 3, wo = w >> 2;

    // load x tile (rows clamped for the 64-row tail tile)
    {
        for (int i = tid; i < 128 * 16; i += 512) {
            int r = i >> 4, c8 = i & 15;
            int n = n0 + r; if (n > 7999) n = 7999;
            uint4 v = *(const uint4*)(g_xnh + ((size_t)k * 8000 + n) * 128 + c8 * 8);
            *(uint4*)&sxn[r * 136 + c8 * 8] = v;
        }
    }

#pragma unroll 1
    for (int ch = 0; ch < 4; ch++) {
        __syncthreads();   // protect sw reuse (prev epilogue reads done)
        for (int i = tid; i < 128 * 16; i += 512) {
            int hl = i >> 4, c8 = i & 15;
            uint4 v = *(const uint4*)(g_w1h + ((size_t)(k * 512 + ch * 128 + hl)) * 128 + c8 * 8);
            *(uint4*)&sw[hl * 136 + c8 * 8] = v;
        }
        __syncthreads();

        wmma::fragment<wmma::accumulator, 16, 16, 16, float> acc[2][2];
#pragma unroll
        for (int mt = 0; mt < 2; mt++)
#pragma unroll
            for (int nt = 0; nt < 2; nt++) wmma::fill_fragment(acc[mt][nt], 0.f);
#pragma unroll
        for (int ks = 0; ks < 8; ks++) {
            wmma::fragment<wmma::matrix_a, 16, 16, 16, __half, wmma::row_major> af[2];
#pragma unroll
            for (int mt = 0; mt < 2; mt++)
                wmma::load_matrix_sync(af[mt], &sxn[(wt * 32 + mt * 16) * 136 + ks * 16], 136);
#pragma unroll
            for (int nt = 0; nt < 2; nt++) {
                wmma::fragment<wmma::matrix_b, 16, 16, 16, __half, wmma::col_major> bf;
                wmma::load_matrix_sync(bf, &sw[(wo * 32 + nt * 16) * 136 + ks * 16], 136);
#pragma unroll
                for (int mt = 0; mt < 2; mt++)
                    wmma::mma_sync(acc[mt][nt], af[mt], bf, acc[mt][nt]);
            }
        }

        // epilogue in two nt sub-steps, reusing sw as f32 [128][68]
#pragma unroll
        for (int nt = 0; nt < 2; nt++) {
            __syncthreads();
#pragma unroll
            for (int mt = 0; mt < 2; mt++)
                wmma::store_matrix_sync(&swf[(wt * 32 + mt * 16) * 68 + wo * 16],
                                        acc[mt][nt], 68, wmma::mem_row_major);
            __syncthreads();
            // cols cc (0..63): wo = cc>>4, within = cc&15; h = ch*128 + wo*32 + nt*16 + within
            for (int i = tid; i < 128 * 32; i += 512) {
                int r = i >> 5, hc = i & 31;        // 32 half2 columns
                int wog = hc >> 3, w2i = hc & 7;
                int cc = wog * 16 + w2i * 2;
                int hcol = ch * 128 + wog * 32 + nt * 16 + w2i * 2;
                float v0 = swf[r * 68 + cc]     + fb1[(size_t)k * 512 + hcol];
                float v1 = swf[r * 68 + cc + 1] + fb1[(size_t)k * 512 + hcol + 1];
                int n = n0 + r;
                if (n < 8000) {
                    __half2 hv = __floats2half2_rn(fast_tanh(v0), fast_tanh(v1));
                    *(__half2*)(g_h + ((size_t)k * 8000 + n) * 512 + hcol) = hv;
                }
            }
        }
    }
}

// ---------------- pass B: fc2 + GLU (f16 mma, smem-staged) ----------------
// grid (63, nBands), 512 threads = 16 warps (wt token 32-rows -> 2 m-frags, wo o-groups)
template <int BW>
__global__ void __launch_bounds__(512, 1) fc2K(const float* __restrict__ fb2,
                                               float* __restrict__ out, int k0) {
    constexpr int O = 12 * BW;
    constexpr int NT16 = (O + 15) / 16;
    constexpr int NTW = (NT16 + 3) / 4;
    constexpr int OP = NT16 * 16;
    extern __shared__ char smraw[];
    __half* sa  = (__half*)smraw;               // [128][136] f16: 34816 B
    __half* sw2 = (__half*)(smraw + 34816);     // [OP][136] f16
    float*  so  = (float*)smraw;                // [128][OP] f32 epilogue (overlays)
    int k = k0 + blockIdx.y;
    int n0 = blockIdx.x * 128;
    int tid = threadIdx.x, w = tid >> 5;
    int wt = w & 3, wo = w >> 2;

    int row0 = d_row0[k];
    int offRows = 0;
    for (int j = 0; j < k; j++) offRows += ((12 * d_bw[j] + 15) / 16) * 16;
    const __half* w2b = g_w2h + (size_t)offRows * 512;

    wmma::fragment<wmma::accumulator, 16, 16, 16, float> acc[2][NTW];
#pragma unroll
    for (int mt = 0; mt < 2; mt++)
#pragma unroll
        for (int i = 0; i < NTW; i++) wmma::fill_fragment(acc[mt][i], 0.f);

#pragma unroll 1
    for (int ck = 0; ck < 4; ck++) {
        __syncthreads();
        for (int i = tid; i < 128 * 16; i += 512) {
            int r = i >> 4, j8 = i & 15;
            int n = n0 + r; if (n > 7999) n = 7999;
            uint4 v = *(const uint4*)(g_h + ((size_t)k * 8000 + n) * 512 + ck * 128 + j8 * 8);
            *(uint4*)&sa[r * 136 + j8 * 8] = v;
        }
        for (int i = tid; i < OP * 16; i += 512) {
            int o = i >> 4, j8 = i & 15;
            uint4 v = *(const uint4*)(w2b + (size_t)o * 512 + ck * 128 + j8 * 8);
            *(uint4*)&sw2[o * 136 + j8 * 8] = v;
        }
        __syncthreads();
#pragma unroll
        for (int ks = 0; ks < 8; ks++) {
            wmma::fragment<wmma::matrix_a, 16, 16, 16, __half, wmma::row_major> af[2];
#pragma unroll
            for (int mt = 0; mt < 2; mt++)
                wmma::load_matrix_sync(af[mt], &sa[(wt * 32 + mt * 16) * 136 + ks * 16], 136);
#pragma unroll
            for (int i = 0; i < NTW; i++) {
                int ot = wo + 4 * i;
                if (ot < NT16) {
                    wmma::fragment<wmma::matrix_b, 16, 16, 16, __half, wmma::col_major> bf;
                    wmma::load_matrix_sync(bf, &sw2[(ot * 16) * 136 + ks * 16], 136);
#pragma unroll
                    for (int mt = 0; mt < 2; mt++)
                        wmma::mma_sync(acc[mt][i], af[mt], bf, acc[mt][i]);
                }
            }
        }
    }

    __syncthreads();   // stage buffers dead; reuse as so
#pragma unroll
    for (int i = 0; i < NTW; i++) {
        int ot = wo + 4 * i;
        if (ot < NT16)
#pragma unroll
            for (int mt = 0; mt < 2; mt++)
                wmma::store_matrix_sync(&so[(wt * 32 + mt * 16) * OP + ot * 16],
                                        acc[mt][i], OP, wmma::mem_row_major);
    }
    __syncthreads();

    constexpr int U = 6 * BW;
    for (int idx = tid; idx < 128 * U; idx += 512) {
        int r = idx / U;
        int u = idx - r * U;
        int n = n0 + r;
        if (n < 8000) {
            float av = so[r * OP + u]     + fb2[(size_t)k * 204 + u];
            float gv = so[r * OP + u + U] + fb2[(size_t)k * 204 + u + U];
            float res = av * fast_sigmoid(gv);
            int b = n / 2000;
            int t = n - b * 2000;
            int ww = u / 6, v = u - ww * 6;
            out[((size_t)((b * 257 + row0 + ww) * 2000 + t)) * 6 + v] = res;
        }
    }
}

// ---------------- checker: validate sampled outputs against exact recompute ----------------
__global__ void checkOut(const float* __restrict__ x,
                         const float* __restrict__ nA, const float* __restrict__ nB,
                         const float* __restrict__ w1, const float* __restrict__ b1,
                         const float* __restrict__ w2, const float* __restrict__ b2,
                         const float* __restrict__ out) {
    __shared__ float sxn[128], shh[512];
    int k = blockIdx.x, s = blockIdx.y;
    int n = (s * 977 + k * 37 + 11) % 8000;
    int b = n / 2000, t = n - b * 2000;
    int bw = d_bw[k], U = 6 * bw, row0 = d_row0[k];
    int tid = threadIdx.x;
    if (tid < 128) {
        float mean = g_stats[(b * 31 + k) * 2];
        float inv  = g_stats[(b * 31 + k) * 2 + 1];
        float wv, bv;
        norm_wb(nA, nB, k * 128 + tid, wv, bv);
        sxn[tid] = (x[(((size_t)(b * 128 + tid)) * 2000 + t) * 31 + k] - mean) * inv * wv + bv;
    }
    __syncthreads();
    for (int hh = tid; hh < 512; hh += 256) {
        const float* wr = w1 + ((size_t)k * 512 + hh) * 128;
        float sacc = b1[k * 512 + hh];
        for (int c = 0; c < 128; c++) sacc += sxn[c] * wr[c];
        shh[hh] = tanhf(sacc);
    }
    __syncthreads();
    for (int u = tid; u < U; u += 256) {
        const float* wa = w2 + ((size_t)k * 204 + u) * 512;
        const float* wg = w2 + ((size_t)k * 204 + u + U) * 512;
        float a = b2[k * 204 + u], g = b2[k * 204 + u + U];
        for (int j = 0; j < 512; j++) { float hv = shh[j]; a += hv * wa[j]; g += hv * wg[j]; }
        float ref = a / (1.f + expf(-g));
        int ww = u / 6, v = u - ww * 6;
        float got = out[((size_t)((b * 257 + row0 + ww) * 2000 + t)) * 6 + v];
        if (fabsf(got - ref) > 0.05f + 0.05f * fabsf(ref)) atomicExch(&g_badOut, 1);
    }
}

// ---------------- guarded naive fallback (verified R9) ----------------
__global__ void __launch_bounds__(256) naiveK(
    const float* __restrict__ x,
    const float* __restrict__ nA, const float* __restrict__ nB,
    const float* __restrict__ w1, const float* __restrict__ b1,
    const float* __restrict__ w2, const float* __restrict__ b2,
    float* __restrict__ out)
{
    if (!g_badOut) return;
    extern __shared__ float sm[];
    float* sxn = sm;                 // [32][132]
    float* sh  = sm + 32 * 132;      // [32][516]
    int k = blockIdx.y;
    int tile = blockIdx.x;
    int bw = d_bw[k];
    int U = 6 * bw;
    int row0 = d_row0[k];
    int tid = threadIdx.x;

    for (int e = tid; e < 32 * 128; e += 256) {
        int i = e >> 7, c = e & 127;
        int n = tile * 32 + i;
        int b = n / 2000, t = n - b * 2000;
        float mean = g_stats[(b * 31 + k) * 2];
        float inv  = g_stats[(b * 31 + k) * 2 + 1];
        float wv, bv;
        norm_wb(nA, nB, k * 128 + c, wv, bv);
        float v = x[(((size_t)(b * 128 + c)) * 2000 + t) * 31 + k];
        sxn[i * 132 + c] = (v - mean) * inv * wv + bv;
    }
    __syncthreads();
    for (int idx = tid; idx < 32 * 512; idx += 256) {
        int hh = idx >> 5, i = idx & 31;
        const float* wr = w1 + ((size_t)k * 512 + hh) * 128;
        float s = b1[k * 512 + hh];
#pragma unroll 8
        for (int c = 0; c < 128; c++) s += sxn[i * 132 + c] * wr[c];
        sh[i * 516 + hh] = tanhf(s);
    }
    __syncthreads();
    for (int idx = tid; idx < 32 * U; idx += 256) {
        int i = idx / U, u = idx - i * U;
        const float* wa = w2 + ((size_t)k * 204 + u) * 512;
        const float* wg = w2 + ((size_t)k * 204 + u + U) * 512;
        float a = b2[k * 204 + u];
        float g = b2[k * 204 + u + U];
#pragma unroll 8
        for (int j = 0; j < 512; j++) {
            float hv = sh[i * 516 + j];
            a += hv * wa[j];
            g += hv * wg[j];
        }
        float res = a / (1.f + expf(-g));
        int n = tile * 32 + i;
        int b = n / 2000, t = n - b * 2000;
        int ww = u / 6, v = u - ww * 6;
        out[((size_t)((b * 257 + row0 + ww) * 2000 + t)) * 6 + v] = res;
    }
}

// ---------------- launch ----------------
static inline int fc2Smem(int BW) {
    int NT16 = (12 * BW + 15) / 16;
    int stage = 34816 + NT16 * 16 * 136 * 2;
    int epi   = 128 * NT16 * 16 * 4;
    return stage > epi ? stage : epi;
}

extern "C" void kernel_launch(void* const* d_in, const int* in_sizes, int n_in,
                              void* d_out, int out_size) {
    const float* x  = (const float*)d_in[0];
    const float* nA = (const float*)d_in[1];
    const float* nB = (const float*)d_in[2];
    const float* w1 = (const float*)d_in[3];
    const float* b1 = (const float*)d_in[4];
    const float* w2 = (const float*)d_in[5];
    const float* b2 = (const float*)d_in[6];
    float* out = (float*)d_out;

    const int SMEM_T2 = 124 * 129 * 4;               // 63,984 B
    const int SMEM_A  = 34816 * 2;                   // 69,632 B
    const int SMEM_NV = (32 * 132 + 32 * 516) * 4;   // 82,944 B

    cudaFuncSetAttribute(normT2h,  cudaFuncAttributeMaxDynamicSharedMemorySize, SMEM_T2);
    cudaFuncSetAttribute(fc1K,     cudaFuncAttributeMaxDynamicSharedMemorySize, SMEM_A);
    cudaFuncSetAttribute(fc2K<2>,  cudaFuncAttributeMaxDynamicSharedMemorySize, fc2Smem(2));
    cudaFuncSetAttribute(fc2K<3>,  cudaFuncAttributeMaxDynamicSharedMemorySize, fc2Smem(3));
    cudaFuncSetAttribute(fc2K<8>,  cudaFuncAttributeMaxDynamicSharedMemorySize, fc2Smem(8));
    cudaFuncSetAttribute(fc2K<16>, cudaFuncAttributeMaxDynamicSharedMemorySize, fc2Smem(16));
    cudaFuncSetAttribute(fc2K<17>, cudaFuncAttributeMaxDynamicSharedMemorySize, fc2Smem(17));
    cudaFuncSetAttribute(naiveK,   cudaFuncAttributeMaxDynamicSharedMemorySize, SMEM_NV);

    resetK<<<1, 1>>>();
    stats1_kernel<<<512, 256>>>(x);
    stats2_kernel<<<124, 128>>>();
    refw1h<<<7936, 256>>>(w1);
    refw2h<<<dim3(31, 13), 256>>>(w2);
    normT2h<<<dim3(500, 4), 256, SMEM_T2>>>(x, nA, nB);

    fc1K<<<dim3(63, 31), 512, SMEM_A>>>(b1);

    fc2K<2><<<dim3(63, 1), 512, fc2Smem(2)>>>(b2, out, 0);
    fc2K<3><<<dim3(63, 10), 512, fc2Smem(3)>>>(b2, out, 1);
    fc2K<8><<<dim3(63, 12), 512, fc2Smem(8)>>>(b2, out, 11);
    fc2K<16><<<dim3(63, 7), 512, fc2Smem(16)>>>(b2, out, 23);
    fc2K<17><<<dim3(63, 1), 512, fc2Smem(17)>>>(b2, out, 30);

    checkOut<<<dim3(31, 8), 256>>>(x, nA, nB, w1, b1, w2, b2, out);
    naiveK<<<dim3(250, 31), 256, SMEM_NV>>>(x, nA, nB, w1, b1, w2, b2, out);
}

// round 14
// speedup vs baseline: 3.4457x; 1.3831x over previous
#include <cuda_runtime.h>
#include <cuda_fp16.h>
#include <mma.h>
#include <cstdint>
#include <cstddef>
#include <math.h>

using namespace nvcuda;

// ---------------- constants ----------------
// B=4, C=128, T=2000, K=31, H=512, N=B*T=8000
// BANDS = {2, 3x10, 8x12, 16x7, 17}; sum=257; O_k = 12*bw_k

__device__ const int d_bw[31]   = {2,3,3,3,3,3,3,3,3,3,3,
                                   8,8,8,8,8,8,8,8,8,8,8,8,
                                   16,16,16,16,16,16,16,17};
__device__ const int d_row0[31] = {0,2,5,8,11,14,17,20,23,26,29,
                                   32,40,48,56,64,72,80,88,96,104,112,
                                   120,128,144,160,176,192,208,224,240};

// ---------------- scratch ----------------
__device__ __half g_xnh[(size_t)31 * 8000 * 128];   // normalized input f16 [k][n][c]
__device__ __half g_h[(size_t)31 * 8000 * 512];     // fc1+tanh output f16 [k][n][h]
__device__ __half g_w1h[(size_t)31 * 512 * 128];    // fc1 weights f16, natural [k][h][c]
__device__ __half g_w2h[(size_t)201 * 16 * 512];    // fc2 weights f16, per-band o-padded [o][j]
__device__ float  g_part[4 * 128 * 62];
__device__ float  g_stats[4 * 31 * 2];              // (mean, invstd) per (b,k)

// ---------------- helpers ----------------
__device__ __forceinline__ float fast_sigmoid(float x) {
    return __fdividef(1.f, 1.f + __expf(-x));
}
__device__ __forceinline__ float fast_tanh(float x) {
    float e = __expf(2.f * x);
    return 1.f - __fdividef(2.f, e + 1.f);
}
__device__ __forceinline__ void norm_wb(const float* nA, const float* nB, int i,
                                        float& wv, float& bv) {
    float va = nA[i], vb = nB[i];
    if (fabsf(va) >= fabsf(vb)) { wv = va; bv = vb; }
    else                        { wv = vb; bv = va; }
}

// ---------------- stats stage 1 (512 threads) ----------------
__global__ void __launch_bounds__(512) stats1_kernel(const float* __restrict__ x) {
    int bc = blockIdx.x;
    const float* p = x + (size_t)bc * 2000 * 31;
    float s[31], q[31];
#pragma unroll
    for (int k = 0; k < 31; k++) { s[k] = 0.f; q[k] = 0.f; }
    for (int t = threadIdx.x; t < 2000; t += 512) {
        const float* pt = p + (size_t)t * 31;
#pragma unroll
        for (int k = 0; k < 31; k++) { float v = pt[k]; s[k] += v; q[k] += v * v; }
    }
    __shared__ float red[16][62];
    int lane = threadIdx.x & 31, w = threadIdx.x >> 5;
#pragma unroll
    for (int k = 0; k < 31; k++) {
#pragma unroll
        for (int o = 16; o; o >>= 1) {
            s[k] += __shfl_down_sync(0xFFFFFFFFu, s[k], o);
            q[k] += __shfl_down_sync(0xFFFFFFFFu, q[k], o);
        }
    }
    if (lane == 0) {
#pragma unroll
        for (int k = 0; k < 31; k++) { red[w][k] = s[k]; red[w][31 + k] = q[k]; }
    }
    __syncthreads();
    if (threadIdx.x < 62) {
        float acc = 0.f;
#pragma unroll
        for (int ww = 0; ww < 16; ww++) acc += red[ww][threadIdx.x];
        g_part[(size_t)bc * 62 + threadIdx.x] = acc;
    }
}

__global__ void stats2_kernel() {
    int b = blockIdx.x / 31, k = blockIdx.x % 31;
    int c = threadIdx.x;
    __shared__ float rs[128], rq[128];
    rs[c] = g_part[(size_t)(b * 128 + c) * 62 + k];
    rq[c] = g_part[(size_t)(b * 128 + c) * 62 + 31 + k];
    __syncthreads();
    for (int o = 64; o; o >>= 1) {
        if (c < o) { rs[c] += rs[c + o]; rq[c] += rq[c + o]; }
        __syncthreads();
    }
    if (c == 0) {
        float m = rs[0] * (1.f / 256000.f);
        float var = rq[0] * (1.f / 256000.f) - m * m;
        g_stats[(b * 31 + k) * 2] = m;
        g_stats[(b * 31 + k) * 2 + 1] = rsqrtf(var + 1e-5f);
    }
}

// ---------------- weight converts ----------------
__global__ void refw1h(const float* __restrict__ w1) {
    size_t i = (size_t)blockIdx.x * 256 + threadIdx.x;   // 7936*256 = 2,031,616
    g_w1h[i] = __float2half(w1[i]);
}
__global__ void refw2h(const float* __restrict__ w2) {
    int k = blockIdx.x, o16 = blockIdx.y;
    int O = 12 * d_bw[k];
    int NT16 = (O + 15) / 16;
    if (o16 >= NT16) return;
    int offRows = 0;
    for (int j = 0; j < k; j++) offRows += ((12 * d_bw[j] + 15) / 16) * 16;
    __half* dst = g_w2h + ((size_t)(offRows + o16 * 16)) * 512;
    for (int i = threadIdx.x; i < 16 * 512; i += 256) {
        int r = i >> 9, j = i & 511;
        int o = o16 * 16 + r;
        float v = (o < O) ? w2[((size_t)k * 204 + o) * 512 + j] : 0.f;
        dst[(size_t)r * 512 + j] = __float2half(v);
    }
}

// ---------------- normT2h (verified): x[B,C,T,K] -> g_xnh[k][n][c] ----------------
__global__ void __launch_bounds__(256) normT2h(const float* __restrict__ x,
                                               const float* __restrict__ nA,
                                               const float* __restrict__ nB) {
    extern __shared__ float sm[];
    int t0 = blockIdx.x * 4, b = blockIdx.y;
    int tid = threadIdx.x;
    for (int idx = tid; idx < 128 * 124; idx += 256) {
        int c = idx / 124, rr = idx - c * 124;
        sm[rr * 129 + c] = x[(((size_t)(b * 128 + c)) * 2000 + t0) * 31 + rr];
    }
    __syncthreads();
    for (int idx = tid; idx < 124 * 128; idx += 256) {
        int rr = idx >> 7, c = idx & 127;
        int ti = rr / 31, k = rr - ti * 31;
        float mean = g_stats[(b * 31 + k) * 2];
        float inv  = g_stats[(b * 31 + k) * 2 + 1];
        float wv, bv;
        norm_wb(nA, nB, k * 128 + c, wv, bv);
        float v = (sm[rr * 129 + c] - mean) * inv * wv + bv;
        g_xnh[((size_t)(k * 8000 + b * 2000 + t0 + ti)) * 128 + c] = __float2half(v);
    }
}

// ---------------- pass A: fc1 + tanh (f16 mma, smem-staged) — verified R13 ----------------
__global__ void __launch_bounds__(512, 2) fc1K(const float* __restrict__ fb1) {
    extern __shared__ char smraw[];
    __half* sxn = (__half*)smraw;               // [128][136] f16: 34816 B
    __half* sw  = (__half*)(smraw + 34816);     // [128][136] f16: 34816 B
    float*  swf = (float*)(smraw + 34816);      // f32 view [128][68] for epilogue reuse
    int k = blockIdx.y;
    int n0 = blockIdx.x * 128;
    int tid = threadIdx.x, w = tid >> 5;
    int wt = w & 3, wo = w >> 2;

    for (int i = tid; i < 128 * 16; i += 512) {
        int r = i >> 4, c8 = i & 15;
        int n = n0 + r; if (n > 7999) n = 7999;
        uint4 v = *(const uint4*)(g_xnh + ((size_t)k * 8000 + n) * 128 + c8 * 8);
        *(uint4*)&sxn[r * 136 + c8 * 8] = v;
    }

#pragma unroll 1
    for (int ch = 0; ch < 4; ch++) {
        __syncthreads();
        for (int i = tid; i < 128 * 16; i += 512) {
            int hl = i >> 4, c8 = i & 15;
            uint4 v = *(const uint4*)(g_w1h + ((size_t)(k * 512 + ch * 128 + hl)) * 128 + c8 * 8);
            *(uint4*)&sw[hl * 136 + c8 * 8] = v;
        }
        __syncthreads();

        wmma::fragment<wmma::accumulator, 16, 16, 16, float> acc[2][2];
#pragma unroll
        for (int mt = 0; mt < 2; mt++)
#pragma unroll
            for (int nt = 0; nt < 2; nt++) wmma::fill_fragment(acc[mt][nt], 0.f);
#pragma unroll
        for (int ks = 0; ks < 8; ks++) {
            wmma::fragment<wmma::matrix_a, 16, 16, 16, __half, wmma::row_major> af[2];
#pragma unroll
            for (int mt = 0; mt < 2; mt++)
                wmma::load_matrix_sync(af[mt], &sxn[(wt * 32 + mt * 16) * 136 + ks * 16], 136);
#pragma unroll
            for (int nt = 0; nt < 2; nt++) {
                wmma::fragment<wmma::matrix_b, 16, 16, 16, __half, wmma::col_major> bf;
                wmma::load_matrix_sync(bf, &sw[(wo * 32 + nt * 16) * 136 + ks * 16], 136);
#pragma unroll
                for (int mt = 0; mt < 2; mt++)
                    wmma::mma_sync(acc[mt][nt], af[mt], bf, acc[mt][nt]);
            }
        }

#pragma unroll
        for (int nt = 0; nt < 2; nt++) {
            __syncthreads();
#pragma unroll
            for (int mt = 0; mt < 2; mt++)
                wmma::store_matrix_sync(&swf[(wt * 32 + mt * 16) * 68 + wo * 16],
                                        acc[mt][nt], 68, wmma::mem_row_major);
            __syncthreads();
            for (int i = tid; i < 128 * 32; i += 512) {
                int r = i >> 5, hc = i & 31;
                int wog = hc >> 3, w2i = hc & 7;
                int cc = wog * 16 + w2i * 2;
                int hcol = ch * 128 + wog * 32 + nt * 16 + w2i * 2;
                float v0 = swf[r * 68 + cc]     + fb1[(size_t)k * 512 + hcol];
                float v1 = swf[r * 68 + cc + 1] + fb1[(size_t)k * 512 + hcol + 1];
                int n = n0 + r;
                if (n < 8000) {
                    __half2 hv = __floats2half2_rn(fast_tanh(v0), fast_tanh(v1));
                    *(__half2*)(g_h + ((size_t)k * 8000 + n) * 512 + hcol) = hv;
                }
            }
        }
    }
}

// ---------------- pass B: fc2 + GLU, unsplit (BW 2/3/8/17) — verified R13 ----------------
template <int BW>
__global__ void __launch_bounds__(512) fc2K(const float* __restrict__ fb2,
                                            float* __restrict__ out, int k0) {
    constexpr int O = 12 * BW;
    constexpr int NT16 = (O + 15) / 16;
    constexpr int NTW = (NT16 + 3) / 4;
    constexpr int OP = NT16 * 16;
    extern __shared__ char smraw[];
    __half* sa  = (__half*)smraw;               // [128][136] f16
    __half* sw2 = (__half*)(smraw + 34816);     // [OP][136] f16
    float*  so  = (float*)smraw;                // [128][OP] f32 (overlays)
    int k = k0 + blockIdx.y;
    int n0 = blockIdx.x * 128;
    int tid = threadIdx.x, w = tid >> 5;
    int wt = w & 3, wo = w >> 2;

    int row0 = d_row0[k];
    int offRows = 0;
    for (int j = 0; j < k; j++) offRows += ((12 * d_bw[j] + 15) / 16) * 16;
    const __half* w2b = g_w2h + (size_t)offRows * 512;

    wmma::fragment<wmma::accumulator, 16, 16, 16, float> acc[2][NTW];
#pragma unroll
    for (int mt = 0; mt < 2; mt++)
#pragma unroll
        for (int i = 0; i < NTW; i++) wmma::fill_fragment(acc[mt][i], 0.f);

#pragma unroll 1
    for (int ck = 0; ck < 4; ck++) {
        __syncthreads();
        for (int i = tid; i < 128 * 16; i += 512) {
            int r = i >> 4, j8 = i & 15;
            int n = n0 + r; if (n > 7999) n = 7999;
            uint4 v = *(const uint4*)(g_h + ((size_t)k * 8000 + n) * 512 + ck * 128 + j8 * 8);
            *(uint4*)&sa[r * 136 + j8 * 8] = v;
        }
        for (int i = tid; i < OP * 16; i += 512) {
            int o = i >> 4, j8 = i & 15;
            uint4 v = *(const uint4*)(w2b + (size_t)o * 512 + ck * 128 + j8 * 8);
            *(uint4*)&sw2[o * 136 + j8 * 8] = v;
        }
        __syncthreads();
#pragma unroll
        for (int ks = 0; ks < 8; ks++) {
            wmma::fragment<wmma::matrix_a, 16, 16, 16, __half, wmma::row_major> af[2];
#pragma unroll
            for (int mt = 0; mt < 2; mt++)
                wmma::load_matrix_sync(af[mt], &sa[(wt * 32 + mt * 16) * 136 + ks * 16], 136);
#pragma unroll
            for (int i = 0; i < NTW; i++) {
                int ot = wo + 4 * i;
                if (ot < NT16) {
                    wmma::fragment<wmma::matrix_b, 16, 16, 16, __half, wmma::col_major> bf;
                    wmma::load_matrix_sync(bf, &sw2[(ot * 16) * 136 + ks * 16], 136);
#pragma unroll
                    for (int mt = 0; mt < 2; mt++)
                        wmma::mma_sync(acc[mt][i], af[mt], bf, acc[mt][i]);
                }
            }
        }
    }

    __syncthreads();
#pragma unroll
    for (int i = 0; i < NTW; i++) {
        int ot = wo + 4 * i;
        if (ot < NT16)
#pragma unroll
            for (int mt = 0; mt < 2; mt++)
                wmma::store_matrix_sync(&so[(wt * 32 + mt * 16) * OP + ot * 16],
                                        acc[mt][i], OP, wmma::mem_row_major);
    }
    __syncthreads();

    constexpr int U = 6 * BW;
    for (int idx = tid; idx < 128 * U; idx += 512) {
        int r = idx / U;
        int u = idx - r * U;
        int n = n0 + r;
        if (n < 8000) {
            float av = so[r * OP + u]     + fb2[(size_t)k * 204 + u];
            float gv = so[r * OP + u + U] + fb2[(size_t)k * 204 + u + U];
            float res = av * fast_sigmoid(gv);
            int b = n / 2000;
            int t = n - b * 2000;
            int ww = u / 6, v = u - ww * 6;
            out[((size_t)((b * 257 + row0 + ww) * 2000 + t)) * 6 + v] = res;
        }
    }
}

// ---------------- pass B split for BW=16: z in {0,1}, GLU-consistent tile pairing ----------------
// block z handles a-tiles [3z,3z+2] (u in [48z,48z+48)) and g-tiles [3z+6,3z+8].
// local tiles l=0..5: physical p = (l<3) ? 3z+l : 3z+3+l  ( = 3z + l + (l>=3)*3 )
__global__ void __launch_bounds__(512) fc2K16(const float* __restrict__ fb2,
                                              float* __restrict__ out, int k0) {
    constexpr int LT = 6;                 // local tiles
    constexpr int LOP = LT * 16;          // 96 local cols
    extern __shared__ char smraw[];
    __half* sa  = (__half*)smraw;               // [128][136]
    __half* sw2 = (__half*)(smraw + 34816);     // [96][136]
    float*  so  = (float*)smraw;                // [128][96] (overlays)
    int k = k0 + blockIdx.y;
    int z = blockIdx.z;
    int n0 = blockIdx.x * 128;
    int tid = threadIdx.x, w = tid >> 5;
    int wt = w & 3, wo = w >> 2;

    int row0 = d_row0[k];
    int offRows = 0;
    for (int j = 0; j < k; j++) offRows += ((12 * d_bw[j] + 15) / 16) * 16;
    const __half* w2b = g_w2h + (size_t)offRows * 512;

    wmma::fragment<wmma::accumulator, 16, 16, 16, float> acc[2][2];  // l = wo, wo+4 (wo+4<6 only wo<2)
#pragma unroll
    for (int mt = 0; mt < 2; mt++)
#pragma unroll
        for (int i = 0; i < 2; i++) wmma::fill_fragment(acc[mt][i], 0.f);

#pragma unroll 1
    for (int ck = 0; ck < 4; ck++) {
        __syncthreads();
        for (int i = tid; i < 128 * 16; i += 512) {
            int r = i >> 4, j8 = i & 15;
            int n = n0 + r; if (n > 7999) n = 7999;
            uint4 v = *(const uint4*)(g_h + ((size_t)k * 8000 + n) * 512 + ck * 128 + j8 * 8);
            *(uint4*)&sa[r * 136 + j8 * 8] = v;
        }
        // stage local tiles: rows lr = l*16 + within; physical o = p*16 + within
        for (int i = tid; i < LOP * 16; i += 512) {
            int lr = i >> 4, j8 = i & 15;
            int l = lr >> 4, within = lr & 15;
            int p = 3 * z + l + ((l >= 3) ? 3 : 0);
            uint4 v = *(const uint4*)(w2b + ((size_t)(p * 16 + within)) * 512 + ck * 128 + j8 * 8);
            *(uint4*)&sw2[lr * 136 + j8 * 8] = v;
        }
        __syncthreads();
#pragma unroll
        for (int ks = 0; ks < 8; ks++) {
            wmma::fragment<wmma::matrix_a, 16, 16, 16, __half, wmma::row_major> af[2];
#pragma unroll
            for (int mt = 0; mt < 2; mt++)
                wmma::load_matrix_sync(af[mt], &sa[(wt * 32 + mt * 16) * 136 + ks * 16], 136);
#pragma unroll
            for (int i = 0; i < 2; i++) {
                int l = wo + 4 * i;
                if (l < LT) {
                    wmma::fragment<wmma::matrix_b, 16, 16, 16, __half, wmma::col_major> bf;
                    wmma::load_matrix_sync(bf, &sw2[(l * 16) * 136 + ks * 16], 136);
#pragma unroll
                    for (int mt = 0; mt < 2; mt++)
                        wmma::mma_sync(acc[mt][i], af[mt], bf, acc[mt][i]);
                }
            }
        }
    }

    __syncthreads();
#pragma unroll
    for (int i = 0; i < 2; i++) {
        int l = wo + 4 * i;
        if (l < LT)
#pragma unroll
            for (int mt = 0; mt < 2; mt++)
                wmma::store_matrix_sync(&so[(wt * 32 + mt * 16) * LOP + l * 16],
                                        acc[mt][i], LOP, wmma::mem_row_major);
    }
    __syncthreads();

    // GLU: local cols 0..47 = a(u), 48..95 = g(u), u = 48z + j
    for (int idx = tid; idx < 128 * 48; idx += 512) {
        int r = idx / 48;
        int j = idx - r * 48;
        int n = n0 + r;
        if (n < 8000) {
            int u = 48 * z + j;
            float av = so[r * LOP + j]      + fb2[(size_t)k * 204 + u];
            float gv = so[r * LOP + 48 + j] + fb2[(size_t)k * 204 + u + 96];
            float res = av * fast_sigmoid(gv);
            int b = n / 2000;
            int t = n - b * 2000;
            int ww = u / 6, v = u - ww * 6;
            out[((size_t)((b * 257 + row0 + ww) * 2000 + t)) * 6 + v] = res;
        }
    }
}

// ---------------- launch ----------------
static inline int fc2Smem(int BW) {
    int NT16 = (12 * BW + 15) / 16;
    int stage = 34816 + NT16 * 16 * 136 * 2;
    int epi   = 128 * NT16 * 16 * 4;
    return stage > epi ? stage : epi;
}

extern "C" void kernel_launch(void* const* d_in, const int* in_sizes, int n_in,
                              void* d_out, int out_size) {
    const float* x  = (const float*)d_in[0];
    const float* nA = (const float*)d_in[1];
    const float* nB = (const float*)d_in[2];
    const float* w1 = (const float*)d_in[3];
    const float* b1 = (const float*)d_in[4];
    const float* w2 = (const float*)d_in[5];
    const float* b2 = (const float*)d_in[6];
    float* out = (float*)d_out;

    const int SMEM_T2 = 124 * 129 * 4;               // 63,984 B
    const int SMEM_A  = 34816 * 2;                   // 69,632 B
    const int SMEM_16 = 34816 + 96 * 136 * 2;        // 60,928 B

    cudaFuncSetAttribute(normT2h,  cudaFuncAttributeMaxDynamicSharedMemorySize, SMEM_T2);
    cudaFuncSetAttribute(fc1K,     cudaFuncAttributeMaxDynamicSharedMemorySize, SMEM_A);
    cudaFuncSetAttribute(fc2K<2>,  cudaFuncAttributeMaxDynamicSharedMemorySize, fc2Smem(2));
    cudaFuncSetAttribute(fc2K<3>,  cudaFuncAttributeMaxDynamicSharedMemorySize, fc2Smem(3));
    cudaFuncSetAttribute(fc2K<8>,  cudaFuncAttributeMaxDynamicSharedMemorySize, fc2Smem(8));
    cudaFuncSetAttribute(fc2K16,   cudaFuncAttributeMaxDynamicSharedMemorySize, SMEM_16);
    cudaFuncSetAttribute(fc2K<17>, cudaFuncAttributeMaxDynamicSharedMemorySize, fc2Smem(17));

    stats1_kernel<<<512, 512>>>(x);
    stats2_kernel<<<124, 128>>>();
    refw1h<<<7936, 256>>>(w1);
    refw2h<<<dim3(31, 13), 256>>>(w2);
    normT2h<<<dim3(500, 4), 256, SMEM_T2>>>(x, nA, nB);

    fc1K<<<dim3(63, 31), 512, SMEM_A>>>(b1);

    fc2K<2><<<dim3(63, 1), 512, fc2Smem(2)>>>(b2, out, 0);
    fc2K<3><<<dim3(63, 10), 512, fc2Smem(3)>>>(b2, out, 1);
    fc2K<8><<<dim3(63, 12), 512, fc2Smem(8)>>>(b2, out, 11);
    fc2K16<<<dim3(63, 7, 2), 512, SMEM_16>>>(b2, out, 23);
    fc2K<17><<<dim3(63, 1), 512, fc2Smem(17)>>>(b2, out, 30);
}

// round 15
// speedup vs baseline: 3.8221x; 1.1092x over previous
#include <cuda_runtime.h>
#include <cuda_fp16.h>
#include <mma.h>
#include <cstdint>
#include <cstddef>
#include <math.h>

using namespace nvcuda;

// ---------------- constants ----------------
// B=4, C=128, T=2000, K=31, H=512, N=B*T=8000
// BANDS = {2, 3x10, 8x12, 16x7, 17}; sum=257; O_k = 12*bw_k

__device__ const int d_bw[31]   = {2,3,3,3,3,3,3,3,3,3,3,
                                   8,8,8,8,8,8,8,8,8,8,8,8,
                                   16,16,16,16,16,16,16,17};
__device__ const int d_row0[31] = {0,2,5,8,11,14,17,20,23,26,29,
                                   32,40,48,56,64,72,80,88,96,104,112,
                                   120,128,144,160,176,192,208,224,240};

// ---------------- scratch ----------------
__device__ __half g_xnh[(size_t)31 * 8000 * 128];   // normalized input f16 [k][n][c]
__device__ __half g_h[(size_t)31 * 8000 * 512];     // fc1+tanh output f16 [k][n][h]
__device__ __half g_w1h[(size_t)31 * 512 * 128];    // fc1 weights f16, natural [k][h][c]
__device__ __half g_w2h[(size_t)201 * 16 * 512];    // fc2 weights f16, per-band o-padded [o][j]
__device__ float  g_part[4 * 128 * 62];
__device__ float  g_stats[4 * 31 * 2];              // (mean, invstd) per (b,k)

// ---------------- helpers ----------------
// reciprocal on FMA pipe only (bit-trick + 2 Newton); rel err ~6e-6 for normal d>0
__device__ __forceinline__ float nr_recip(float d) {
    float y = __uint_as_float(0x7EF311C3u - __float_as_uint(d));
    y = y * (2.f - d * y);
    y = y * (2.f - d * y);
    return y;
}
__device__ __forceinline__ float fast_tanh(float x) {
    x = fminf(fmaxf(x, -10.f), 10.f);
    float e = __expf(2.f * x);           // 1 MUFU
    return 1.f - 2.f * nr_recip(e + 1.f);
}
__device__ __forceinline__ float fast_sigmoid(float x) {
    x = fminf(fmaxf(x, -30.f), 30.f);
    float e = __expf(-x);                // 1 MUFU
    return nr_recip(1.f + e);
}
__device__ __forceinline__ void norm_wb(const float* nA, const float* nB, int i,
                                        float& wv, float& bv) {
    float va = nA[i], vb = nB[i];
    if (fabsf(va) >= fabsf(vb)) { wv = va; bv = vb; }
    else                        { wv = vb; bv = va; }
}
__device__ __forceinline__ void cpa16(void* s, const void* g) {
    unsigned sa = (unsigned)__cvta_generic_to_shared(s);
    asm volatile("cp.async.cg.shared.global [%0], [%1], 16;" :: "r"(sa), "l"(g));
}
#define CPA_COMMIT() asm volatile("cp.async.commit_group;")
#define CPA_WAIT(n)  asm volatile("cp.async.wait_group %0;" :: "n"(n))

// ---------------- stats stage 1 (512 threads) ----------------
__global__ void __launch_bounds__(512) stats1_kernel(const float* __restrict__ x) {
    int bc = blockIdx.x;
    const float* p = x + (size_t)bc * 2000 * 31;
    float s[31], q[31];
#pragma unroll
    for (int k = 0; k < 31; k++) { s[k] = 0.f; q[k] = 0.f; }
    for (int t = threadIdx.x; t < 2000; t += 512) {
        const float* pt = p + (size_t)t * 31;
#pragma unroll
        for (int k = 0; k < 31; k++) { float v = pt[k]; s[k] += v; q[k] += v * v; }
    }
    __shared__ float red[16][62];
    int lane = threadIdx.x & 31, w = threadIdx.x >> 5;
#pragma unroll
    for (int k = 0; k < 31; k++) {
#pragma unroll
        for (int o = 16; o; o >>= 1) {
            s[k] += __shfl_down_sync(0xFFFFFFFFu, s[k], o);
            q[k] += __shfl_down_sync(0xFFFFFFFFu, q[k], o);
        }
    }
    if (lane == 0) {
#pragma unroll
        for (int k = 0; k < 31; k++) { red[w][k] = s[k]; red[w][31 + k] = q[k]; }
    }
    __syncthreads();
    if (threadIdx.x < 62) {
        float acc = 0.f;
#pragma unroll
        for (int ww = 0; ww < 16; ww++) acc += red[ww][threadIdx.x];
        g_part[(size_t)bc * 62 + threadIdx.x] = acc;
    }
}

__global__ void stats2_kernel() {
    int b = blockIdx.x / 31, k = blockIdx.x % 31;
    int c = threadIdx.x;
    __shared__ float rs[128], rq[128];
    rs[c] = g_part[(size_t)(b * 128 + c) * 62 + k];
    rq[c] = g_part[(size_t)(b * 128 + c) * 62 + 31 + k];
    __syncthreads();
    for (int o = 64; o; o >>= 1) {
        if (c < o) { rs[c] += rs[c + o]; rq[c] += rq[c + o]; }
        __syncthreads();
    }
    if (c == 0) {
        float m = rs[0] * (1.f / 256000.f);
        float var = rq[0] * (1.f / 256000.f) - m * m;
        g_stats[(b * 31 + k) * 2] = m;
        g_stats[(b * 31 + k) * 2 + 1] = rsqrtf(var + 1e-5f);
    }
}

// ---------------- weight converts ----------------
__global__ void refw1h(const float* __restrict__ w1) {
    size_t i = (size_t)blockIdx.x * 256 + threadIdx.x;   // 7936*256 = 2,031,616
    g_w1h[i] = __float2half(w1[i]);
}
__global__ void refw2h(const float* __restrict__ w2) {
    int k = blockIdx.x, o16 = blockIdx.y;
    int O = 12 * d_bw[k];
    int NT16 = (O + 15) / 16;
    if (o16 >= NT16) return;
    int offRows = 0;
    for (int j = 0; j < k; j++) offRows += ((12 * d_bw[j] + 15) / 16) * 16;
    __half* dst = g_w2h + ((size_t)(offRows + o16 * 16)) * 512;
    for (int i = threadIdx.x; i < 16 * 512; i += 256) {
        int r = i >> 9, j = i & 511;
        int o = o16 * 16 + r;
        float v = (o < O) ? w2[((size_t)k * 204 + o) * 512 + j] : 0.f;
        dst[(size_t)r * 512 + j] = __float2half(v);
    }
}

// ---------------- normT2h (verified): x[B,C,T,K] -> g_xnh[k][n][c] ----------------
__global__ void __launch_bounds__(256) normT2h(const float* __restrict__ x,
                                               const float* __restrict__ nA,
                                               const float* __restrict__ nB) {
    extern __shared__ float sm[];
    int t0 = blockIdx.x * 4, b = blockIdx.y;
    int tid = threadIdx.x;
    for (int idx = tid; idx < 128 * 124; idx += 256) {
        int c = idx / 124, rr = idx - c * 124;
        sm[rr * 129 + c] = x[(((size_t)(b * 128 + c)) * 2000 + t0) * 31 + rr];
    }
    __syncthreads();
    for (int idx = tid; idx < 124 * 128; idx += 256) {
        int rr = idx >> 7, c = idx & 127;
        int ti = rr / 31, k = rr - ti * 31;
        float mean = g_stats[(b * 31 + k) * 2];
        float inv  = g_stats[(b * 31 + k) * 2 + 1];
        float wv, bv;
        norm_wb(nA, nB, k * 128 + c, wv, bv);
        float v = (sm[rr * 129 + c] - mean) * inv * wv + bv;
        g_xnh[((size_t)(k * 8000 + b * 2000 + t0 + ti)) * 128 + c] = __float2half(v);
    }
}

// ---------------- pass A: fc1 + tanh — cp.async double-buffered W1 ----------------
__global__ void __launch_bounds__(512) fc1K(const float* __restrict__ fb1) {
    extern __shared__ char smraw[];
    __half* sxn = (__half*)smraw;                        // [128][136] f16: 34816 B
    __half* wb0 = (__half*)(smraw + 34816);              // W1 buffer 0
    __half* wb1 = (__half*)(smraw + 2 * 34816);          // W1 buffer 1
    int k = blockIdx.y;
    int n0 = blockIdx.x * 128;
    int tid = threadIdx.x, w = tid >> 5;
    int wt = w & 3, wo = w >> 2;

    // group0: sx tile + W1 chunk0; group1: W1 chunk1
    for (int i = tid; i < 128 * 16; i += 512) {
        int r = i >> 4, c8 = i & 15;
        int n = n0 + r; if (n > 7999) n = 7999;
        cpa16(&sxn[r * 136 + c8 * 8], g_xnh + ((size_t)k * 8000 + n) * 128 + c8 * 8);
    }
    for (int i = tid; i < 128 * 16; i += 512) {
        int hl = i >> 4, c8 = i & 15;
        cpa16(&wb0[hl * 136 + c8 * 8], g_w1h + ((size_t)(k * 512 + hl)) * 128 + c8 * 8);
    }
    CPA_COMMIT();
    for (int i = tid; i < 128 * 16; i += 512) {
        int hl = i >> 4, c8 = i & 15;
        cpa16(&wb1[hl * 136 + c8 * 8], g_w1h + ((size_t)(k * 512 + 128 + hl)) * 128 + c8 * 8);
    }
    CPA_COMMIT();

#pragma unroll 1
    for (int ch = 0; ch < 4; ch++) {
        __half* wb = (ch & 1) ? wb1 : wb0;
        if (ch == 3) { CPA_WAIT(0); } else { CPA_WAIT(1); }
        __syncthreads();

        wmma::fragment<wmma::accumulator, 16, 16, 16, float> acc[2][2];
#pragma unroll
        for (int mt = 0; mt < 2; mt++)
#pragma unroll
            for (int nt = 0; nt < 2; nt++) wmma::fill_fragment(acc[mt][nt], 0.f);
#pragma unroll
        for (int ks = 0; ks < 8; ks++) {
            wmma::fragment<wmma::matrix_a, 16, 16, 16, __half, wmma::row_major> af[2];
#pragma unroll
            for (int mt = 0; mt < 2; mt++)
                wmma::load_matrix_sync(af[mt], &sxn[(wt * 32 + mt * 16) * 136 + ks * 16], 136);
#pragma unroll
            for (int nt = 0; nt < 2; nt++) {
                wmma::fragment<wmma::matrix_b, 16, 16, 16, __half, wmma::col_major> bf;
                wmma::load_matrix_sync(bf, &wb[(wo * 32 + nt * 16) * 136 + ks * 16], 136);
#pragma unroll
                for (int mt = 0; mt < 2; mt++)
                    wmma::mma_sync(acc[mt][nt], af[mt], bf, acc[mt][nt]);
            }
        }
        __syncthreads();   // all warps done reading wb

        float* swf = (float*)wb;          // [128][68] f32 scratch overlays current W1 buf
#pragma unroll
        for (int nt = 0; nt < 2; nt++) {
#pragma unroll
            for (int mt = 0; mt < 2; mt++)
                wmma::store_matrix_sync(&swf[(wt * 32 + mt * 16) * 68 + wo * 16],
                                        acc[mt][nt], 68, wmma::mem_row_major);
            __syncthreads();
            for (int i = tid; i < 128 * 32; i += 512) {
                int r = i >> 5, hc = i & 31;
                int wog = hc >> 3, w2i = hc & 7;
                int cc = wog * 16 + w2i * 2;
                int hcol = ch * 128 + wog * 32 + nt * 16 + w2i * 2;
                float v0 = swf[r * 68 + cc]     + fb1[(size_t)k * 512 + hcol];
                float v1 = swf[r * 68 + cc + 1] + fb1[(size_t)k * 512 + hcol + 1];
                int n = n0 + r;
                if (n < 8000) {
                    __half2 hv = __floats2half2_rn(fast_tanh(v0), fast_tanh(v1));
                    *(__half2*)(g_h + ((size_t)k * 8000 + n) * 512 + hcol) = hv;
                }
            }
            __syncthreads();
        }
        // prefetch W1 chunk ch+2 into the buffer just freed
        if (ch < 2) {
            for (int i = tid; i < 128 * 16; i += 512) {
                int hl = i >> 4, c8 = i & 15;
                cpa16(&wb[hl * 136 + c8 * 8],
                      g_w1h + ((size_t)(k * 512 + (ch + 2) * 128 + hl)) * 128 + c8 * 8);
            }
            CPA_COMMIT();
        }
    }
}

// ---------------- pass B: fc2 + GLU, unsplit (BW 2/3/8/17), cp.async staging ----------------
template <int BW>
__global__ void __launch_bounds__(512) fc2K(const float* __restrict__ fb2,
                                            float* __restrict__ out, int k0) {
    constexpr int O = 12 * BW;
    constexpr int NT16 = (O + 15) / 16;
    constexpr int NTW = (NT16 + 3) / 4;
    constexpr int OP = NT16 * 16;
    extern __shared__ char smraw[];
    __half* sa  = (__half*)smraw;               // [128][136] f16
    __half* sw2 = (__half*)(smraw + 34816);     // [OP][136] f16
    float*  so  = (float*)smraw;                // [128][OP] f32 (overlays)
    int k = k0 + blockIdx.y;
    int n0 = blockIdx.x * 128;
    int tid = threadIdx.x, w = tid >> 5;
    int wt = w & 3, wo = w >> 2;

    int row0 = d_row0[k];
    int offRows = 0;
    for (int j = 0; j < k; j++) offRows += ((12 * d_bw[j] + 15) / 16) * 16;
    const __half* w2b = g_w2h + (size_t)offRows * 512;

    wmma::fragment<wmma::accumulator, 16, 16, 16, float> acc[2][NTW];
#pragma unroll
    for (int mt = 0; mt < 2; mt++)
#pragma unroll
        for (int i = 0; i < NTW; i++) wmma::fill_fragment(acc[mt][i], 0.f);

#pragma unroll 1
    for (int ck = 0; ck < 4; ck++) {
        __syncthreads();
        for (int i = tid; i < 128 * 16; i += 512) {
            int r = i >> 4, j8 = i & 15;
            int n = n0 + r; if (n > 7999) n = 7999;
            cpa16(&sa[r * 136 + j8 * 8],
                  g_h + ((size_t)k * 8000 + n) * 512 + ck * 128 + j8 * 8);
        }
        for (int i = tid; i < OP * 16; i += 512) {
            int o = i >> 4, j8 = i & 15;
            cpa16(&sw2[o * 136 + j8 * 8], w2b + (size_t)o * 512 + ck * 128 + j8 * 8);
        }
        CPA_COMMIT();
        CPA_WAIT(0);
        __syncthreads();
#pragma unroll
        for (int ks = 0; ks < 8; ks++) {
            wmma::fragment<wmma::matrix_a, 16, 16, 16, __half, wmma::row_major> af[2];
#pragma unroll
            for (int mt = 0; mt < 2; mt++)
                wmma::load_matrix_sync(af[mt], &sa[(wt * 32 + mt * 16) * 136 + ks * 16], 136);
#pragma unroll
            for (int i = 0; i < NTW; i++) {
                int ot = wo + 4 * i;
                if (ot < NT16) {
                    wmma::fragment<wmma::matrix_b, 16, 16, 16, __half, wmma::col_major> bf;
                    wmma::load_matrix_sync(bf, &sw2[(ot * 16) * 136 + ks * 16], 136);
#pragma unroll
                    for (int mt = 0; mt < 2; mt++)
                        wmma::mma_sync(acc[mt][i], af[mt], bf, acc[mt][i]);
                }
            }
        }
    }

    __syncthreads();
#pragma unroll
    for (int i = 0; i < NTW; i++) {
        int ot = wo + 4 * i;
        if (ot < NT16)
#pragma unroll
            for (int mt = 0; mt < 2; mt++)
                wmma::store_matrix_sync(&so[(wt * 32 + mt * 16) * OP + ot * 16],
                                        acc[mt][i], OP, wmma::mem_row_major);
    }
    __syncthreads();

    constexpr int U = 6 * BW;
    for (int idx = tid; idx < 128 * U; idx += 512) {
        int r = idx / U;
        int u = idx - r * U;
        int n = n0 + r;
        if (n < 8000) {
            float av = so[r * OP + u]     + fb2[(size_t)k * 204 + u];
            float gv = so[r * OP + u + U] + fb2[(size_t)k * 204 + u + U];
            float res = av * fast_sigmoid(gv);
            int b = n / 2000;
            int t = n - b * 2000;
            int ww = u / 6, v = u - ww * 6;
            out[((size_t)((b * 257 + row0 + ww) * 2000 + t)) * 6 + v] = res;
        }
    }
}

// ---------------- pass B split for BW=16 (z in {0,1}), cp.async staging ----------------
__global__ void __launch_bounds__(512) fc2K16(const float* __restrict__ fb2,
                                              float* __restrict__ out, int k0) {
    constexpr int LT = 6;
    constexpr int LOP = LT * 16;          // 96
    extern __shared__ char smraw[];
    __half* sa  = (__half*)smraw;               // [128][136]
    __half* sw2 = (__half*)(smraw + 34816);     // [96][136]
    float*  so  = (float*)smraw;                // [128][96] (overlays)
    int k = k0 + blockIdx.y;
    int z = blockIdx.z;
    int n0 = blockIdx.x * 128;
    int tid = threadIdx.x, w = tid >> 5;
    int wt = w & 3, wo = w >> 2;

    int row0 = d_row0[k];
    int offRows = 0;
    for (int j = 0; j < k; j++) offRows += ((12 * d_bw[j] + 15) / 16) * 16;
    const __half* w2b = g_w2h + (size_t)offRows * 512;

    wmma::fragment<wmma::accumulator, 16, 16, 16, float> acc[2][2];
#pragma unroll
    for (int mt = 0; mt < 2; mt++)
#pragma unroll
        for (int i = 0; i < 2; i++) wmma::fill_fragment(acc[mt][i], 0.f);

#pragma unroll 1
    for (int ck = 0; ck < 4; ck++) {
        __syncthreads();
        for (int i = tid; i < 128 * 16; i += 512) {
            int r = i >> 4, j8 = i & 15;
            int n = n0 + r; if (n > 7999) n = 7999;
            cpa16(&sa[r * 136 + j8 * 8],
                  g_h + ((size_t)k * 8000 + n) * 512 + ck * 128 + j8 * 8);
        }
        for (int i = tid; i < LOP * 16; i += 512) {
            int lr = i >> 4, j8 = i & 15;
            int l = lr >> 4, within = lr & 15;
            int p = 3 * z + l + ((l >= 3) ? 3 : 0);
            cpa16(&sw2[lr * 136 + j8 * 8],
                  w2b + ((size_t)(p * 16 + within)) * 512 + ck * 128 + j8 * 8);
        }
        CPA_COMMIT();
        CPA_WAIT(0);
        __syncthreads();
#pragma unroll
        for (int ks = 0; ks < 8; ks++) {
            wmma::fragment<wmma::matrix_a, 16, 16, 16, __half, wmma::row_major> af[2];
#pragma unroll
            for (int mt = 0; mt < 2; mt++)
                wmma::load_matrix_sync(af[mt], &sa[(wt * 32 + mt * 16) * 136 + ks * 16], 136);
#pragma unroll
            for (int i = 0; i < 2; i++) {
                int l = wo + 4 * i;
                if (l < LT) {
                    wmma::fragment<wmma::matrix_b, 16, 16, 16, __half, wmma::col_major> bf;
                    wmma::load_matrix_sync(bf, &sw2[(l * 16) * 136 + ks * 16], 136);
#pragma unroll
                    for (int mt = 0; mt < 2; mt++)
                        wmma::mma_sync(acc[mt][i], af[mt], bf, acc[mt][i]);
                }
            }
        }
    }

    __syncthreads();
#pragma unroll
    for (int i = 0; i < 2; i++) {
        int l = wo + 4 * i;
        if (l < LT)
#pragma unroll
            for (int mt = 0; mt < 2; mt++)
                wmma::store_matrix_sync(&so[(wt * 32 + mt * 16) * LOP + l * 16],
                                        acc[mt][i], LOP, wmma::mem_row_major);
    }
    __syncthreads();

    for (int idx = tid; idx < 128 * 48; idx += 512) {
        int r = idx / 48;
        int j = idx - r * 48;
        int n = n0 + r;
        if (n < 8000) {
            int u = 48 * z + j;
            float av = so[r * LOP + j]      + fb2[(size_t)k * 204 + u];
            float gv = so[r * LOP + 48 + j] + fb2[(size_t)k * 204 + u + 96];
            float res = av * fast_sigmoid(gv);
            int b = n / 2000;
            int t = n - b * 2000;
            int ww = u / 6, v = u - ww * 6;
            out[((size_t)((b * 257 + row0 + ww) * 2000 + t)) * 6 + v] = res;
        }
    }
}

// ---------------- launch ----------------
static inline int fc2Smem(int BW) {
    int NT16 = (12 * BW + 15) / 16;
    int stage = 34816 + NT16 * 16 * 136 * 2;
    int epi   = 128 * NT16 * 16 * 4;
    return stage > epi ? stage : epi;
}

extern "C" void kernel_launch(void* const* d_in, const int* in_sizes, int n_in,
                              void* d_out, int out_size) {
    const float* x  = (const float*)d_in[0];
    const float* nA = (const float*)d_in[1];
    const float* nB = (const float*)d_in[2];
    const float* w1 = (const float*)d_in[3];
    const float* b1 = (const float*)d_in[4];
    const float* w2 = (const float*)d_in[5];
    const float* b2 = (const float*)d_in[6];
    float* out = (float*)d_out;

    const int SMEM_T2 = 124 * 129 * 4;               // 63,984 B
    const int SMEM_A  = 3 * 34816;                   // 104,448 B
    const int SMEM_16 = 34816 + 96 * 136 * 2;        // 60,928 B

    cudaFuncSetAttribute(normT2h,  cudaFuncAttributeMaxDynamicSharedMemorySize, SMEM_T2);
    cudaFuncSetAttribute(fc1K,     cudaFuncAttributeMaxDynamicSharedMemorySize, SMEM_A);
    cudaFuncSetAttribute(fc2K<2>,  cudaFuncAttributeMaxDynamicSharedMemorySize, fc2Smem(2));
    cudaFuncSetAttribute(fc2K<3>,  cudaFuncAttributeMaxDynamicSharedMemorySize, fc2Smem(3));
    cudaFuncSetAttribute(fc2K<8>,  cudaFuncAttributeMaxDynamicSharedMemorySize, fc2Smem(8));
    cudaFuncSetAttribute(fc2K16,   cudaFuncAttributeMaxDynamicSharedMemorySize, SMEM_16);
    cudaFuncSetAttribute(fc2K<17>, cudaFuncAttributeMaxDynamicSharedMemorySize, fc2Smem(17));

    stats1_kernel<<<512, 512>>>(x);
    stats2_kernel<<<124, 128>>>();
    refw1h<<<7936, 256>>>(w1);
    refw2h<<<dim3(31, 13), 256>>>(w2);
    normT2h<<<dim3(500, 4), 256, SMEM_T2>>>(x, nA, nB);

    fc1K<<<dim3(63, 31), 512, SMEM_A>>>(b1);

    fc2K<2><<<dim3(63, 1), 512, fc2Smem(2)>>>(b2, out, 0);
    fc2K<3><<<dim3(63, 10), 512, fc2Smem(3)>>>(b2, out, 1);
    fc2K<8><<<dim3(63, 12), 512, fc2Smem(8)>>>(b2, out, 11);
    fc2K16<<<dim3(63, 7, 2), 512, SMEM_16>>>(b2, out, 23);
    fc2K<17><<<dim3(63, 1), 512, fc2Smem(17)>>>(b2, out, 30);
}

// round 16
// speedup vs baseline: 3.8448x; 1.0060x over previous
#include <cuda_runtime.h>
#include <cuda_fp16.h>
#include <mma.h>
#include <cstdint>
#include <cstddef>
#include <math.h>

using namespace nvcuda;

// ---------------- constants ----------------
// B=4, C=128, T=2000, K=31, H=512, N=B*T=8000
// BANDS = {2, 3x10, 8x12, 16x7, 17}; sum=257; O_k = 12*bw_k; U_k = 6*bw_k

__device__ const int d_bw[31]   = {2,3,3,3,3,3,3,3,3,3,3,
                                   8,8,8,8,8,8,8,8,8,8,8,8,
                                   16,16,16,16,16,16,16,17};
__device__ const int d_row0[31] = {0,2,5,8,11,14,17,20,23,26,29,
                                   32,40,48,56,64,72,80,88,96,104,112,
                                   120,128,144,160,176,192,208,224,240};
// UP = ceil(6*bw/16)*16 : per-half padded col count
__device__ const int d_UP[31]   = {16,32,32,32,32,32,32,32,32,32,32,
                                   48,48,48,48,48,48,48,48,48,48,48,48,
                                   96,96,96,96,96,96,96,112};
// fc2U worklist: 60 groups of (band, a-tile base)
__device__ const int g_gk[60] = {0,
 1,2,3,4,5,6,7,8,9,10,
 11,11,12,12,13,13,14,14,15,15,16,16,17,17,18,18,19,19,20,20,21,21,22,22,
 23,23,23,24,24,24,25,25,25,26,26,26,27,27,27,28,28,28,29,29,29,
 30,30,30,30};
__device__ const int g_gtb[60] = {0,
 0,0,0,0,0,0,0,0,0,0,
 0,2,0,2,0,2,0,2,0,2,0,2,0,2,0,2,0,2,0,2,0,2,0,2,
 0,2,4,0,2,4,0,2,4,0,2,4,0,2,4,0,2,4,0,2,4,
 0,2,4,6};

// ---------------- scratch ----------------
__device__ __half g_xnh[(size_t)31 * 8000 * 128];   // normalized input f16 [k][n][c]
__device__ __half g_h[(size_t)31 * 8000 * 512];     // fc1+tanh output f16 [k][n][h]
__device__ __half g_w1h[(size_t)31 * 512 * 128];    // fc1 weights f16, natural [k][h][c]
__device__ __half g_w2h[(size_t)3392 * 512];        // fc2 weights f16, split-padded a/g halves
__device__ float  g_part[4 * 128 * 62];
__device__ float  g_stats[4 * 31 * 2];              // (mean, invstd) per (b,k)

// ---------------- helpers ----------------
__device__ __forceinline__ float nr_recip(float d) {
    float y = __uint_as_float(0x7EF311C3u - __float_as_uint(d));
    y = y * (2.f - d * y);
    y = y * (2.f - d * y);
    return y;
}
__device__ __forceinline__ float fast_tanh(float x) {
    x = fminf(fmaxf(x, -10.f), 10.f);
    float e = __expf(2.f * x);
    return 1.f - 2.f * nr_recip(e + 1.f);
}
__device__ __forceinline__ float fast_sigmoid(float x) {
    x = fminf(fmaxf(x, -30.f), 30.f);
    float e = __expf(-x);
    return nr_recip(1.f + e);
}
__device__ __forceinline__ void norm_wb(const float* nA, const float* nB, int i,
                                        float& wv, float& bv) {
    float va = nA[i], vb = nB[i];
    if (fabsf(va) >= fabsf(vb)) { wv = va; bv = vb; }
    else                        { wv = vb; bv = va; }
}
__device__ __forceinline__ void cpa16(void* s, const void* g) {
    unsigned sa = (unsigned)__cvta_generic_to_shared(s);
    asm volatile("cp.async.cg.shared.global [%0], [%1], 16;" :: "r"(sa), "l"(g));
}
#define CPA_COMMIT() asm volatile("cp.async.commit_group;")
#define CPA_WAIT(n)  asm volatile("cp.async.wait_group %0;" :: "n"(n))

// ---------------- stats stage 1 (512 threads) ----------------
__global__ void __launch_bounds__(512) stats1_kernel(const float* __restrict__ x) {
    int bc = blockIdx.x;
    const float* p = x + (size_t)bc * 2000 * 31;
    float s[31], q[31];
#pragma unroll
    for (int k = 0; k < 31; k++) { s[k] = 0.f; q[k] = 0.f; }
    for (int t = threadIdx.x; t < 2000; t += 512) {
        const float* pt = p + (size_t)t * 31;
#pragma unroll
        for (int k = 0; k < 31; k++) { float v = pt[k]; s[k] += v; q[k] += v * v; }
    }
    __shared__ float red[16][62];
    int lane = threadIdx.x & 31, w = threadIdx.x >> 5;
#pragma unroll
    for (int k = 0; k < 31; k++) {
#pragma unroll
        for (int o = 16; o; o >>= 1) {
            s[k] += __shfl_down_sync(0xFFFFFFFFu, s[k], o);
            q[k] += __shfl_down_sync(0xFFFFFFFFu, q[k], o);
        }
    }
    if (lane == 0) {
#pragma unroll
        for (int k = 0; k < 31; k++) { red[w][k] = s[k]; red[w][31 + k] = q[k]; }
    }
    __syncthreads();
    if (threadIdx.x < 62) {
        float acc = 0.f;
#pragma unroll
        for (int ww = 0; ww < 16; ww++) acc += red[ww][threadIdx.x];
        g_part[(size_t)bc * 62 + threadIdx.x] = acc;
    }
}

__global__ void stats2_kernel() {
    int b = blockIdx.x / 31, k = blockIdx.x % 31;
    int c = threadIdx.x;
    __shared__ float rs[128], rq[128];
    rs[c] = g_part[(size_t)(b * 128 + c) * 62 + k];
    rq[c] = g_part[(size_t)(b * 128 + c) * 62 + 31 + k];
    __syncthreads();
    for (int o = 64; o; o >>= 1) {
        if (c < o) { rs[c] += rs[c + o]; rq[c] += rq[c + o]; }
        __syncthreads();
    }
    if (c == 0) {
        float m = rs[0] * (1.f / 256000.f);
        float var = rq[0] * (1.f / 256000.f) - m * m;
        g_stats[(b * 31 + k) * 2] = m;
        g_stats[(b * 31 + k) * 2 + 1] = rsqrtf(var + 1e-5f);
    }
}

// ---------------- weight converts ----------------
__global__ void refw1h(const float* __restrict__ w1) {
    size_t i = (size_t)blockIdx.x * 256 + threadIdx.x;   // 7936*256 = 2,031,616
    g_w1h[i] = __float2half(w1[i]);
}
// fc2 repack: per band, rows [0,UP) = a-half (source o = r, valid r<U),
// rows [UP,2UP) = g-half (source o = U + (r-UP), valid r-UP<U). 16-row groups.
__global__ void refw2h(const float* __restrict__ w2) {
    int k = blockIdx.x, rg = blockIdx.y;        // rg: 16-row group, up to 14
    int UP = d_UP[k];
    int U = 6 * d_bw[k];
    int totRows = 2 * UP;
    if (rg * 16 >= totRows) return;
    int off = 0;
    for (int j = 0; j < k; j++) off += 2 * d_UP[j];
    __half* dst = g_w2h + ((size_t)(off + rg * 16)) * 512;
    for (int i = threadIdx.x; i < 16 * 512; i += 256) {
        int r = i >> 9, j = i & 511;
        int row = rg * 16 + r;
        int src;
        bool valid;
        if (row < UP) { src = row;          valid = (row < U); }
        else          { src = U + row - UP; valid = (row - UP < U); }
        float v = valid ? w2[((size_t)k * 204 + src) * 512 + j] : 0.f;
        dst[(size_t)r * 512 + j] = __float2half(v);
    }
}

// ---------------- normT2h (verified): x[B,C,T,K] -> g_xnh[k][n][c] ----------------
__global__ void __launch_bounds__(256) normT2h(const float* __restrict__ x,
                                               const float* __restrict__ nA,
                                               const float* __restrict__ nB) {
    extern __shared__ float sm[];
    int t0 = blockIdx.x * 4, b = blockIdx.y;
    int tid = threadIdx.x;
    for (int idx = tid; idx < 128 * 124; idx += 256) {
        int c = idx / 124, rr = idx - c * 124;
        sm[rr * 129 + c] = x[(((size_t)(b * 128 + c)) * 2000 + t0) * 31 + rr];
    }
    __syncthreads();
    for (int idx = tid; idx < 124 * 128; idx += 256) {
        int rr = idx >> 7, c = idx & 127;
        int ti = rr / 31, k = rr - ti * 31;
        float mean = g_stats[(b * 31 + k) * 2];
        float inv  = g_stats[(b * 31 + k) * 2 + 1];
        float wv, bv;
        norm_wb(nA, nB, k * 128 + c, wv, bv);
        float v = (sm[rr * 129 + c] - mean) * inv * wv + bv;
        g_xnh[((size_t)(k * 8000 + b * 2000 + t0 + ti)) * 128 + c] = __float2half(v);
    }
}

// ---------------- pass A: fc1 + tanh — cp.async double-buffered W1 (verified R15) ----------------
__global__ void __launch_bounds__(512) fc1K(const float* __restrict__ fb1) {
    extern __shared__ char smraw[];
    __half* sxn = (__half*)smraw;                        // [128][136]
    __half* wb0 = (__half*)(smraw + 34816);
    __half* wb1 = (__half*)(smraw + 2 * 34816);
    int k = blockIdx.y;
    int n0 = blockIdx.x * 128;
    int tid = threadIdx.x, w = tid >> 5;
    int wt = w & 3, wo = w >> 2;

    for (int i = tid; i < 128 * 16; i += 512) {
        int r = i >> 4, c8 = i & 15;
        int n = n0 + r; if (n > 7999) n = 7999;
        cpa16(&sxn[r * 136 + c8 * 8], g_xnh + ((size_t)k * 8000 + n) * 128 + c8 * 8);
    }
    for (int i = tid; i < 128 * 16; i += 512) {
        int hl = i >> 4, c8 = i & 15;
        cpa16(&wb0[hl * 136 + c8 * 8], g_w1h + ((size_t)(k * 512 + hl)) * 128 + c8 * 8);
    }
    CPA_COMMIT();
    for (int i = tid; i < 128 * 16; i += 512) {
        int hl = i >> 4, c8 = i & 15;
        cpa16(&wb1[hl * 136 + c8 * 8], g_w1h + ((size_t)(k * 512 + 128 + hl)) * 128 + c8 * 8);
    }
    CPA_COMMIT();

#pragma unroll 1
    for (int ch = 0; ch < 4; ch++) {
        __half* wb = (ch & 1) ? wb1 : wb0;
        if (ch == 3) { CPA_WAIT(0); } else { CPA_WAIT(1); }
        __syncthreads();

        wmma::fragment<wmma::accumulator, 16, 16, 16, float> acc[2][2];
#pragma unroll
        for (int mt = 0; mt < 2; mt++)
#pragma unroll
            for (int nt = 0; nt < 2; nt++) wmma::fill_fragment(acc[mt][nt], 0.f);
#pragma unroll
        for (int ks = 0; ks < 8; ks++) {
            wmma::fragment<wmma::matrix_a, 16, 16, 16, __half, wmma::row_major> af[2];
#pragma unroll
            for (int mt = 0; mt < 2; mt++)
                wmma::load_matrix_sync(af[mt], &sxn[(wt * 32 + mt * 16) * 136 + ks * 16], 136);
#pragma unroll
            for (int nt = 0; nt < 2; nt++) {
                wmma::fragment<wmma::matrix_b, 16, 16, 16, __half, wmma::col_major> bf;
                wmma::load_matrix_sync(bf, &wb[(wo * 32 + nt * 16) * 136 + ks * 16], 136);
#pragma unroll
                for (int mt = 0; mt < 2; mt++)
                    wmma::mma_sync(acc[mt][nt], af[mt], bf, acc[mt][nt]);
            }
        }
        __syncthreads();

        float* swf = (float*)wb;          // [128][68] f32 scratch overlays current W1 buf
#pragma unroll
        for (int nt = 0; nt < 2; nt++) {
#pragma unroll
            for (int mt = 0; mt < 2; mt++)
                wmma::store_matrix_sync(&swf[(wt * 32 + mt * 16) * 68 + wo * 16],
                                        acc[mt][nt], 68, wmma::mem_row_major);
            __syncthreads();
            for (int i = tid; i < 128 * 32; i += 512) {
                int r = i >> 5, hc = i & 31;
                int wog = hc >> 3, w2i = hc & 7;
                int cc = wog * 16 + w2i * 2;
                int hcol = ch * 128 + wog * 32 + nt * 16 + w2i * 2;
                float v0 = swf[r * 68 + cc]     + fb1[(size_t)k * 512 + hcol];
                float v1 = swf[r * 68 + cc + 1] + fb1[(size_t)k * 512 + hcol + 1];
                int n = n0 + r;
                if (n < 8000) {
                    __half2 hv = __floats2half2_rn(fast_tanh(v0), fast_tanh(v1));
                    *(__half2*)(g_h + ((size_t)k * 8000 + n) * 512 + hcol) = hv;
                }
            }
            __syncthreads();
        }
        if (ch < 2) {
            for (int i = tid; i < 128 * 16; i += 512) {
                int hl = i >> 4, c8 = i & 15;
                cpa16(&wb[hl * 136 + c8 * 8],
                      g_w1h + ((size_t)(k * 512 + (ch + 2) * 128 + hl)) * 128 + c8 * 8);
            }
            CPA_COMMIT();
        }
    }
}

// ---------------- unified pass B: fc2 + GLU, one uniform launch ----------------
// grid (63, 60): 128 tokens x worklist group (band k, a-tile base tb).
// Block covers a-tiles {tb, tb+1} and their GLU partners g-tiles {tb, tb+1}.
// smem: sa [128][136] f16 + sw2 [64][136] f16 (stage) / so [128][64] f32 (epilogue).
__global__ void __launch_bounds__(512) fc2U(const float* __restrict__ fb2,
                                            float* __restrict__ out) {
    extern __shared__ char smraw[];
    __half* sa  = (__half*)smraw;               // [128][136]
    __half* sw2 = (__half*)(smraw + 34816);     // [64][136]
    float*  so  = (float*)smraw;                // [128][64] (overlays)
    int grp = blockIdx.y;
    int k  = g_gk[grp];
    int tb = g_gtb[grp];
    int n0 = blockIdx.x * 128;
    int tid = threadIdx.x, w = tid >> 5;
    int wt = w & 3, wo = w >> 2;

    int UP = d_UP[k];
    int ATp = UP >> 4;               // padded a-tile count
    int U = 6 * d_bw[k];
    int row0 = d_row0[k];
    int off = 0;
    for (int j = 0; j < k; j++) off += 2 * d_UP[j];
    const __half* w2b = g_w2h + (size_t)off * 512;

    wmma::fragment<wmma::accumulator, 16, 16, 16, float> acc[2];
#pragma unroll
    for (int mt = 0; mt < 2; mt++) wmma::fill_fragment(acc[mt], 0.f);

#pragma unroll 1
    for (int ck = 0; ck < 4; ck++) {
        __syncthreads();
        for (int i = tid; i < 128 * 16; i += 512) {
            int r = i >> 4, j8 = i & 15;
            int n = n0 + r; if (n > 7999) n = 7999;
            cpa16(&sa[r * 136 + j8 * 8],
                  g_h + ((size_t)k * 8000 + n) * 512 + ck * 128 + j8 * 8);
        }
        // stage 4 local tiles: l=0,1 -> a-tiles tb+l ; l=2,3 -> g-tiles tb+(l-2)
        for (int i = tid; i < 64 * 16; i += 512) {
            int lr = i >> 4, j8 = i & 15;
            int l = lr >> 4, rr = lr & 15;
            int at = tb + ((l < 2) ? l : (l - 2));
            int pr;
            if (at < ATp) pr = ((l < 2) ? 0 : UP) + at * 16 + rr;
            else          pr = 0;            // dead tile; epilogue guards u<U
            cpa16(&sw2[lr * 136 + j8 * 8], w2b + (size_t)pr * 512 + ck * 128 + j8 * 8);
        }
        CPA_COMMIT();
        CPA_WAIT(0);
        __syncthreads();
#pragma unroll
        for (int ks = 0; ks < 8; ks++) {
            wmma::fragment<wmma::matrix_a, 16, 16, 16, __half, wmma::row_major> af[2];
#pragma unroll
            for (int mt = 0; mt < 2; mt++)
                wmma::load_matrix_sync(af[mt], &sa[(wt * 32 + mt * 16) * 136 + ks * 16], 136);
            wmma::fragment<wmma::matrix_b, 16, 16, 16, __half, wmma::col_major> bf;
            wmma::load_matrix_sync(bf, &sw2[(wo * 16) * 136 + ks * 16], 136);
#pragma unroll
            for (int mt = 0; mt < 2; mt++)
                wmma::mma_sync(acc[mt], af[mt], bf, acc[mt]);
        }
    }

    __syncthreads();   // stage buffers dead; reuse as so
#pragma unroll
    for (int mt = 0; mt < 2; mt++)
        wmma::store_matrix_sync(&so[(wt * 32 + mt * 16) * 64 + wo * 16],
                                acc[mt], 64, wmma::mem_row_major);
    __syncthreads();

    // GLU: cols 0..31 = a (u = tb*16 + j), cols 32..63 = matching g
    for (int idx = tid; idx < 128 * 32; idx += 512) {
        int r = idx >> 5;
        int j = idx & 31;
        int u = tb * 16 + j;
        int n = n0 + r;
        if (u < U && n < 8000) {
            float av = so[r * 64 + j]      + fb2[(size_t)k * 204 + u];
            float gv = so[r * 64 + 32 + j] + fb2[(size_t)k * 204 + U + u];
            float res = av * fast_sigmoid(gv);
            int b = n / 2000;
            int t = n - b * 2000;
            int ww = u / 6, v = u - ww * 6;
            out[((size_t)((b * 257 + row0 + ww) * 2000 + t)) * 6 + v] = res;
        }
    }
}

// ---------------- launch ----------------
extern "C" void kernel_launch(void* const* d_in, const int* in_sizes, int n_in,
                              void* d_out, int out_size) {
    const float* x  = (const float*)d_in[0];
    const float* nA = (const float*)d_in[1];
    const float* nB = (const float*)d_in[2];
    const float* w1 = (const float*)d_in[3];
    const float* b1 = (const float*)d_in[4];
    const float* w2 = (const float*)d_in[5];
    const float* b2 = (const float*)d_in[6];
    float* out = (float*)d_out;

    const int SMEM_T2 = 124 * 129 * 4;               // 63,984 B
    const int SMEM_A  = 3 * 34816;                   // 104,448 B
    const int SMEM_U  = 34816 + 64 * 136 * 2;        // 52,224 B

    cudaFuncSetAttribute(normT2h, cudaFuncAttributeMaxDynamicSharedMemorySize, SMEM_T2);
    cudaFuncSetAttribute(fc1K,    cudaFuncAttributeMaxDynamicSharedMemorySize, SMEM_A);
    cudaFuncSetAttribute(fc2U,    cudaFuncAttributeMaxDynamicSharedMemorySize, SMEM_U);

    stats1_kernel<<<512, 512>>>(x);
    stats2_kernel<<<124, 128>>>();
    refw1h<<<7936, 256>>>(w1);
    refw2h<<<dim3(31, 14), 256>>>(w2);
    normT2h<<<dim3(500, 4), 256, SMEM_T2>>>(x, nA, nB);

    fc1K<<<dim3(63, 31), 512, SMEM_A>>>(b1);
    fc2U<<<dim3(63, 60), 512, SMEM_U>>>(b2, out);
}

// round 17
// speedup vs baseline: 3.8849x; 1.0104x over previous
#include <cuda_runtime.h>
#include <cuda_fp16.h>
#include <mma.h>
#include <cstdint>
#include <cstddef>
#include <math.h>

using namespace nvcuda;

// ---------------- constants ----------------
// B=4, C=128, T=2000, K=31, H=512, N=B*T=8000
// BANDS = {2, 3x10, 8x12, 16x7, 17}; sum=257; O_k = 12*bw_k; U_k = 6*bw_k

__device__ const int d_bw[31]   = {2,3,3,3,3,3,3,3,3,3,3,
                                   8,8,8,8,8,8,8,8,8,8,8,8,
                                   16,16,16,16,16,16,16,17};
__device__ const int d_row0[31] = {0,2,5,8,11,14,17,20,23,26,29,
                                   32,40,48,56,64,72,80,88,96,104,112,
                                   120,128,144,160,176,192,208,224,240};
// UP = ceil(6*bw/16)*16 : per-half padded col count
__device__ const int d_UP[31]   = {16,32,32,32,32,32,32,32,32,32,32,
                                   48,48,48,48,48,48,48,48,48,48,48,48,
                                   96,96,96,96,96,96,96,112};
// fc2U worklist: 60 groups of (band, a-tile base)
__device__ const int g_gk[60] = {0,
 1,2,3,4,5,6,7,8,9,10,
 11,11,12,12,13,13,14,14,15,15,16,16,17,17,18,18,19,19,20,20,21,21,22,22,
 23,23,23,24,24,24,25,25,25,26,26,26,27,27,27,28,28,28,29,29,29,
 30,30,30,30};
__device__ const int g_gtb[60] = {0,
 0,0,0,0,0,0,0,0,0,0,
 0,2,0,2,0,2,0,2,0,2,0,2,0,2,0,2,0,2,0,2,0,2,0,2,
 0,2,4,0,2,4,0,2,4,0,2,4,0,2,4,0,2,4,0,2,4,
 0,2,4,6};

// ---------------- scratch ----------------
__device__ __half g_xnh[(size_t)31 * 8000 * 128];   // normalized input f16 [k][n][c]
__device__ __half g_h[(size_t)31 * 8000 * 512];     // fc1+tanh output f16 [k][n][h]
__device__ __half g_w1h[(size_t)31 * 512 * 128];    // fc1 weights f16, natural [k][h][c]
__device__ __half g_w2h[(size_t)3392 * 512];        // fc2 weights f16, split-padded a/g halves
__device__ float  g_part[4 * 128 * 62];
__device__ float  g_stats[4 * 31 * 2];              // (mean, invstd) per (b,k)

// ---------------- helpers ----------------
__device__ __forceinline__ float nr_recip(float d) {
    float y = __uint_as_float(0x7EF311C3u - __float_as_uint(d));
    y = y * (2.f - d * y);
    y = y * (2.f - d * y);
    return y;
}
__device__ __forceinline__ float fast_tanh(float x) {
    x = fminf(fmaxf(x, -10.f), 10.f);
    float e = __expf(2.f * x);
    return 1.f - 2.f * nr_recip(e + 1.f);
}
__device__ __forceinline__ float fast_sigmoid(float x) {
    x = fminf(fmaxf(x, -30.f), 30.f);
    float e = __expf(-x);
    return nr_recip(1.f + e);
}
__device__ __forceinline__ void norm_wb(const float* nA, const float* nB, int i,
                                        float& wv, float& bv) {
    float va = nA[i], vb = nB[i];
    if (fabsf(va) >= fabsf(vb)) { wv = va; bv = vb; }
    else                        { wv = vb; bv = va; }
}
__device__ __forceinline__ void cpa16(void* s, const void* g) {
    unsigned sa = (unsigned)__cvta_generic_to_shared(s);
    asm volatile("cp.async.cg.shared.global [%0], [%1], 16;" :: "r"(sa), "l"(g));
}
#define CPA_COMMIT() asm volatile("cp.async.commit_group;")
#define CPA_WAIT(n)  asm volatile("cp.async.wait_group %0;" :: "n"(n))

// ---------------- stats stage 1 (512 threads) ----------------
__global__ void __launch_bounds__(512) stats1_kernel(const float* __restrict__ x) {
    int bc = blockIdx.x;
    const float* p = x + (size_t)bc * 2000 * 31;
    float s[31], q[31];
#pragma unroll
    for (int k = 0; k < 31; k++) { s[k] = 0.f; q[k] = 0.f; }
    for (int t = threadIdx.x; t < 2000; t += 512) {
        const float* pt = p + (size_t)t * 31;
#pragma unroll
        for (int k = 0; k < 31; k++) { float v = pt[k]; s[k] += v; q[k] += v * v; }
    }
    __shared__ float red[16][62];
    int lane = threadIdx.x & 31, w = threadIdx.x >> 5;
#pragma unroll
    for (int k = 0; k < 31; k++) {
#pragma unroll
        for (int o = 16; o; o >>= 1) {
            s[k] += __shfl_down_sync(0xFFFFFFFFu, s[k], o);
            q[k] += __shfl_down_sync(0xFFFFFFFFu, q[k], o);
        }
    }
    if (lane == 0) {
#pragma unroll
        for (int k = 0; k < 31; k++) { red[w][k] = s[k]; red[w][31 + k] = q[k]; }
    }
    __syncthreads();
    if (threadIdx.x < 62) {
        float acc = 0.f;
#pragma unroll
        for (int ww = 0; ww < 16; ww++) acc += red[ww][threadIdx.x];
        g_part[(size_t)bc * 62 + threadIdx.x] = acc;
    }
}

__global__ void stats2_kernel() {
    int b = blockIdx.x / 31, k = blockIdx.x % 31;
    int c = threadIdx.x;
    __shared__ float rs[128], rq[128];
    rs[c] = g_part[(size_t)(b * 128 + c) * 62 + k];
    rq[c] = g_part[(size_t)(b * 128 + c) * 62 + 31 + k];
    __syncthreads();
    for (int o = 64; o; o >>= 1) {
        if (c < o) { rs[c] += rs[c + o]; rq[c] += rq[c + o]; }
        __syncthreads();
    }
    if (c == 0) {
        float m = rs[0] * (1.f / 256000.f);
        float var = rq[0] * (1.f / 256000.f) - m * m;
        g_stats[(b * 31 + k) * 2] = m;
        g_stats[(b * 31 + k) * 2 + 1] = rsqrtf(var + 1e-5f);
    }
}

// ---------------- weight converts ----------------
__global__ void refw1h(const float* __restrict__ w1) {
    size_t i = (size_t)blockIdx.x * 256 + threadIdx.x;   // 7936*256 = 2,031,616
    g_w1h[i] = __float2half(w1[i]);
}
// fc2 repack: per band, rows [0,UP) = a-half (source o = r, valid r<U),
// rows [UP,2UP) = g-half (source o = U + (r-UP), valid r-UP<U). 16-row groups.
__global__ void refw2h(const float* __restrict__ w2) {
    int k = blockIdx.x, rg = blockIdx.y;        // rg: 16-row group, up to 14
    int UP = d_UP[k];
    int U = 6 * d_bw[k];
    int totRows = 2 * UP;
    if (rg * 16 >= totRows) return;
    int off = 0;
    for (int j = 0; j < k; j++) off += 2 * d_UP[j];
    __half* dst = g_w2h + ((size_t)(off + rg * 16)) * 512;
    for (int i = threadIdx.x; i < 16 * 512; i += 256) {
        int r = i >> 9, j = i & 511;
        int row = rg * 16 + r;
        int src;
        bool valid;
        if (row < UP) { src = row;          valid = (row < U); }
        else          { src = U + row - UP; valid = (row - UP < U); }
        float v = valid ? w2[((size_t)k * 204 + src) * 512 + j] : 0.f;
        dst[(size_t)r * 512 + j] = __float2half(v);
    }
}

// ---------------- normT2h (512 threads): x[B,C,T,K] -> g_xnh[k][n][c] ----------------
__global__ void __launch_bounds__(512) normT2h(const float* __restrict__ x,
                                               const float* __restrict__ nA,
                                               const float* __restrict__ nB) {
    extern __shared__ float sm[];
    int t0 = blockIdx.x * 4, b = blockIdx.y;
    int tid = threadIdx.x;
    for (int idx = tid; idx < 128 * 124; idx += 512) {
        int c = idx / 124, rr = idx - c * 124;
        sm[rr * 129 + c] = x[(((size_t)(b * 128 + c)) * 2000 + t0) * 31 + rr];
    }
    __syncthreads();
    for (int idx = tid; idx < 124 * 128; idx += 512) {
        int rr = idx >> 7, c = idx & 127;
        int ti = rr / 31, k = rr - ti * 31;
        float mean = g_stats[(b * 31 + k) * 2];
        float inv  = g_stats[(b * 31 + k) * 2 + 1];
        float wv, bv;
        norm_wb(nA, nB, k * 128 + c, wv, bv);
        float v = (sm[rr * 129 + c] - mean) * inv * wv + bv;
        g_xnh[((size_t)(k * 8000 + b * 2000 + t0 + ti)) * 128 + c] = __float2half(v);
    }
}

// ---------------- pass A: fc1 + tanh — cp.async double-buffered W1 (verified R15) ----------------
__global__ void __launch_bounds__(512) fc1K(const float* __restrict__ fb1) {
    extern __shared__ char smraw[];
    __half* sxn = (__half*)smraw;                        // [128][136]
    __half* wb0 = (__half*)(smraw + 34816);
    __half* wb1 = (__half*)(smraw + 2 * 34816);
    int k = blockIdx.y;
    int n0 = blockIdx.x * 128;
    int tid = threadIdx.x, w = tid >> 5;
    int wt = w & 3, wo = w >> 2;

    for (int i = tid; i < 128 * 16; i += 512) {
        int r = i >> 4, c8 = i & 15;
        int n = n0 + r; if (n > 7999) n = 7999;
        cpa16(&sxn[r * 136 + c8 * 8], g_xnh + ((size_t)k * 8000 + n) * 128 + c8 * 8);
    }
    for (int i = tid; i < 128 * 16; i += 512) {
        int hl = i >> 4, c8 = i & 15;
        cpa16(&wb0[hl * 136 + c8 * 8], g_w1h + ((size_t)(k * 512 + hl)) * 128 + c8 * 8);
    }
    CPA_COMMIT();
    for (int i = tid; i < 128 * 16; i += 512) {
        int hl = i >> 4, c8 = i & 15;
        cpa16(&wb1[hl * 136 + c8 * 8], g_w1h + ((size_t)(k * 512 + 128 + hl)) * 128 + c8 * 8);
    }
    CPA_COMMIT();

#pragma unroll 1
    for (int ch = 0; ch < 4; ch++) {
        __half* wb = (ch & 1) ? wb1 : wb0;
        if (ch == 3) { CPA_WAIT(0); } else { CPA_WAIT(1); }
        __syncthreads();

        wmma::fragment<wmma::accumulator, 16, 16, 16, float> acc[2][2];
#pragma unroll
        for (int mt = 0; mt < 2; mt++)
#pragma unroll
            for (int nt = 0; nt < 2; nt++) wmma::fill_fragment(acc[mt][nt], 0.f);
#pragma unroll
        for (int ks = 0; ks < 8; ks++) {
            wmma::fragment<wmma::matrix_a, 16, 16, 16, __half, wmma::row_major> af[2];
#pragma unroll
            for (int mt = 0; mt < 2; mt++)
                wmma::load_matrix_sync(af[mt], &sxn[(wt * 32 + mt * 16) * 136 + ks * 16], 136);
#pragma unroll
            for (int nt = 0; nt < 2; nt++) {
                wmma::fragment<wmma::matrix_b, 16, 16, 16, __half, wmma::col_major> bf;
                wmma::load_matrix_sync(bf, &wb[(wo * 32 + nt * 16) * 136 + ks * 16], 136);
#pragma unroll
                for (int mt = 0; mt < 2; mt++)
                    wmma::mma_sync(acc[mt][nt], af[mt], bf, acc[mt][nt]);
            }
        }
        __syncthreads();

        float* swf = (float*)wb;          // [128][68] f32 scratch overlays current W1 buf
#pragma unroll
        for (int nt = 0; nt < 2; nt++) {
#pragma unroll
            for (int mt = 0; mt < 2; mt++)
                wmma::store_matrix_sync(&swf[(wt * 32 + mt * 16) * 68 + wo * 16],
                                        acc[mt][nt], 68, wmma::mem_row_major);
            __syncthreads();
            for (int i = tid; i < 128 * 32; i += 512) {
                int r = i >> 5, hc = i & 31;
                int wog = hc >> 3, w2i = hc & 7;
                int cc = wog * 16 + w2i * 2;
                int hcol = ch * 128 + wog * 32 + nt * 16 + w2i * 2;
                float v0 = swf[r * 68 + cc]     + fb1[(size_t)k * 512 + hcol];
                float v1 = swf[r * 68 + cc + 1] + fb1[(size_t)k * 512 + hcol + 1];
                int n = n0 + r;
                if (n < 8000) {
                    __half2 hv = __floats2half2_rn(fast_tanh(v0), fast_tanh(v1));
                    *(__half2*)(g_h + ((size_t)k * 8000 + n) * 512 + hcol) = hv;
                }
            }
            __syncthreads();
        }
        if (ch < 2) {
            for (int i = tid; i < 128 * 16; i += 512) {
                int hl = i >> 4, c8 = i & 15;
                cpa16(&wb[hl * 136 + c8 * 8],
                      g_w1h + ((size_t)(k * 512 + (ch + 2) * 128 + hl)) * 128 + c8 * 8);
            }
            CPA_COMMIT();
        }
    }
}

// ---------------- unified pass B: fc2 + GLU, 256-token tiles ----------------
// grid (32, 60): 256 tokens x worklist group (band k, a-tile base tb).
// Block covers a-tiles {tb, tb+1} and their GLU partners g-tiles {tb, tb+1}.
// smem: sa [256][136] f16 (69632 B) + sw2 [64][136] f16 (17408 B) = 87040 B;
// epilogue so [256][64] f32 (65536 B) overlays.
__global__ void __launch_bounds__(512) fc2U(const float* __restrict__ fb2,
                                            float* __restrict__ out) {
    extern __shared__ char smraw[];
    __half* sa  = (__half*)smraw;               // [256][136]
    __half* sw2 = (__half*)(smraw + 69632);     // [64][136]
    float*  so  = (float*)smraw;                // [256][64] (overlays)
    int grp = blockIdx.y;
    int k  = g_gk[grp];
    int tb = g_gtb[grp];
    int n0 = blockIdx.x * 256;
    int tid = threadIdx.x, w = tid >> 5;
    int wt = w & 3, wo = w >> 2;                // wt: 64-row group; wo: 16-col tile

    int UP = d_UP[k];
    int ATp = UP >> 4;
    int U = 6 * d_bw[k];
    int row0 = d_row0[k];
    int off = 0;
    for (int j = 0; j < k; j++) off += 2 * d_UP[j];
    const __half* w2b = g_w2h + (size_t)off * 512;

    wmma::fragment<wmma::accumulator, 16, 16, 16, float> acc[4];
#pragma unroll
    for (int mt = 0; mt < 4; mt++) wmma::fill_fragment(acc[mt], 0.f);

#pragma unroll 1
    for (int ck = 0; ck < 4; ck++) {
        __syncthreads();
        for (int i = tid; i < 256 * 16; i += 512) {
            int r = i >> 4, j8 = i & 15;
            int n = n0 + r; if (n > 7999) n = 7999;
            cpa16(&sa[r * 136 + j8 * 8],
                  g_h + ((size_t)k * 8000 + n) * 512 + ck * 128 + j8 * 8);
        }
        for (int i = tid; i < 64 * 16; i += 512) {
            int lr = i >> 4, j8 = i & 15;
            int l = lr >> 4, rr = lr & 15;
            int at = tb + ((l < 2) ? l : (l - 2));
            int pr;
            if (at < ATp) pr = ((l < 2) ? 0 : UP) + at * 16 + rr;
            else          pr = 0;            // dead tile; epilogue guards u<U
            cpa16(&sw2[lr * 136 + j8 * 8], w2b + (size_t)pr * 512 + ck * 128 + j8 * 8);
        }
        CPA_COMMIT();
        CPA_WAIT(0);
        __syncthreads();
#pragma unroll
        for (int ks = 0; ks < 8; ks++) {
            wmma::fragment<wmma::matrix_b, 16, 16, 16, __half, wmma::col_major> bf;
            wmma::load_matrix_sync(bf, &sw2[(wo * 16) * 136 + ks * 16], 136);
#pragma unroll
            for (int mt = 0; mt < 4; mt++) {
                wmma::fragment<wmma::matrix_a, 16, 16, 16, __half, wmma::row_major> af;
                wmma::load_matrix_sync(af, &sa[(wt * 64 + mt * 16) * 136 + ks * 16], 136);
                wmma::mma_sync(acc[mt], af, bf, acc[mt]);
            }
        }
    }

    __syncthreads();   // stage buffers dead; reuse as so
#pragma unroll
    for (int mt = 0; mt < 4; mt++)
        wmma::store_matrix_sync(&so[(wt * 64 + mt * 16) * 64 + wo * 16],
                                acc[mt], 64, wmma::mem_row_major);
    __syncthreads();

    // GLU: cols 0..31 = a (u = tb*16 + j), cols 32..63 = matching g
    for (int idx = tid; idx < 256 * 32; idx += 512) {
        int r = idx >> 5;
        int j = idx & 31;
        int u = tb * 16 + j;
        int n = n0 + r;
        if (u < U && n < 8000) {
            float av = so[r * 64 + j]      + fb2[(size_t)k * 204 + u];
            float gv = so[r * 64 + 32 + j] + fb2[(size_t)k * 204 + U + u];
            float res = av * fast_sigmoid(gv);
            int b = n / 2000;
            int t = n - b * 2000;
            int ww = u / 6, v = u - ww * 6;
            out[((size_t)((b * 257 + row0 + ww) * 2000 + t)) * 6 + v] = res;
        }
    }
}

// ---------------- launch ----------------
extern "C" void kernel_launch(void* const* d_in, const int* in_sizes, int n_in,
                              void* d_out, int out_size) {
    const float* x  = (const float*)d_in[0];
    const float* nA = (const float*)d_in[1];
    const float* nB = (const float*)d_in[2];
    const float* w1 = (const float*)d_in[3];
    const float* b1 = (const float*)d_in[4];
    const float* w2 = (const float*)d_in[5];
    const float* b2 = (const float*)d_in[6];
    float* out = (float*)d_out;

    const int SMEM_T2 = 124 * 129 * 4;               // 63,984 B
    const int SMEM_A  = 3 * 34816;                   // 104,448 B
    const int SMEM_U  = 69632 + 17408;               // 87,040 B

    cudaFuncSetAttribute(normT2h, cudaFuncAttributeMaxDynamicSharedMemorySize, SMEM_T2);
    cudaFuncSetAttribute(fc1K,    cudaFuncAttributeMaxDynamicSharedMemorySize, SMEM_A);
    cudaFuncSetAttribute(fc2U,    cudaFuncAttributeMaxDynamicSharedMemorySize, SMEM_U);

    // order chosen so an ncu skip-5 capture lands on fc1K
    refw1h<<<7936, 256>>>(w1);
    refw2h<<<dim3(31, 14), 256>>>(w2);
    stats1_kernel<<<512, 512>>>(x);
    stats2_kernel<<<124, 128>>>();
    normT2h<<<dim3(500, 4), 512, SMEM_T2>>>(x, nA, nB);

    fc1K<<<dim3(63, 31), 512, SMEM_A>>>(b1);
    fc2U<<<dim3(32, 60), 512, SMEM_U>>>(b2, out);
}